// round 10
// baseline (speedup 1.0000x reference)
#include <cuda_runtime.h>
#include <cuda_bf16.h>
#include <math.h>
#include <stdint.h>

// ---------------------------------------------------------------------------
// Problem constants
// ---------------------------------------------------------------------------
#define BATCH 2
#define SEQ   2048
#define DIM   2048
#define NH    16
#define DK    128
#define DV    128
#define MTOT  (BATCH * SEQ)          // 4096
#define NELEM (MTOT * DIM)           // 8388608
#define WSZ   (DIM * DIM)            // 4194304

// ---------------------------------------------------------------------------
// Device scratch
// ---------------------------------------------------------------------------
__device__ float g_qpre[NELEM];          // also reused as normalized-o buffer
__device__ float g_kpre[NELEM];
__device__ float g_vpre[NELEM];
__device__ float g_q[NELEM];
__device__ float g_k[NELEM];
__device__ float g_v[NELEM];
__device__ float g_gate[NELEM];
__device__ float g_g[NELEM];
__device__ float g_o[NELEM];
__device__ float g_f1[MTOT * DV];
__device__ float g_beta[MTOT * NH];

// bf16 split buffers (gate path only)
__device__ __nv_bfloat16 g_xh[NELEM],  g_xl[NELEM];
__device__ __nv_bfloat16 g_wf1h[DIM*DV], g_wf1l[DIM*DV];
__device__ __nv_bfloat16 g_wf2h[DV*DIM], g_wf2l[DV*DIM];
__device__ __nv_bfloat16 g_f1h[MTOT*DV], g_f1l[MTOT*DV];

// int8 quant buffers
__device__ int8_t g_xq1[NELEM], g_xq2[NELEM];
__device__ int8_t g_oq1[NELEM], g_oq2[NELEM];
__device__ int8_t g_q1wq[WSZ], g_q2wq[WSZ];
__device__ int8_t g_q1wk[WSZ], g_q2wk[WSZ];
__device__ int8_t g_q1wv[WSZ], g_q2wv[WSZ];
__device__ int8_t g_q1wg[WSZ], g_q2wg[WSZ];
__device__ int8_t g_q1wo[WSZ], g_q2wo[WSZ];
__device__ float g_saX[MTOT], g_saO[MTOT];
__device__ float g_sbq[DIM], g_sbk[DIM], g_sbv[DIM], g_sbg[DIM], g_sbo[DIM];

// ---------------------------------------------------------------------------
// PTX helpers
// ---------------------------------------------------------------------------
__device__ __forceinline__ uint32_t smem_u32(const void* p) {
    uint32_t a;
    asm("{ .reg .u64 t; cvta.to.shared.u64 t, %1; cvt.u32.u64 %0, t; }"
        : "=r"(a) : "l"(p));
    return a;
}

#define CP16(dst, src) \
    asm volatile("cp.async.cg.shared.global [%0], [%1], 16;" \
                 :: "r"(dst), "l"(src))
#define CP_COMMIT() asm volatile("cp.async.commit_group;" ::: "memory")
#define CP_WAIT0()  asm volatile("cp.async.wait_group 0;" ::: "memory")
#define CP_WAIT1()  asm volatile("cp.async.wait_group 1;" ::: "memory")

#define LDSM4(R, addr)                                                         \
    asm volatile("ldmatrix.sync.aligned.m8n8.x4.shared.b16 {%0,%1,%2,%3}, [%4];" \
        : "=r"((R)[0]), "=r"((R)[1]), "=r"((R)[2]), "=r"((R)[3]) : "r"(addr))

#define LDSM4T(R, addr)                                                        \
    asm volatile("ldmatrix.sync.aligned.m8n8.x4.trans.shared.b16 {%0,%1,%2,%3}, [%4];" \
        : "=r"((R)[0]), "=r"((R)[1]), "=r"((R)[2]), "=r"((R)[3]) : "r"(addr))

#define MMA16816(C4, A4, b0, b1)                                               \
    asm volatile("mma.sync.aligned.m16n8k16.row.col.f32.bf16.bf16.f32 "        \
        "{%0,%1,%2,%3},{%4,%5,%6,%7},{%8,%9},{%0,%1,%2,%3};"                   \
        : "+f"((C4)[0]), "+f"((C4)[1]), "+f"((C4)[2]), "+f"((C4)[3])           \
        : "r"((A4)[0]), "r"((A4)[1]), "r"((A4)[2]), "r"((A4)[3]),              \
          "r"(b0), "r"(b1))

#define IMMA16832(C4, A4, b0, b1)                                              \
    asm volatile("mma.sync.aligned.m16n8k32.row.col.s32.s8.s8.s32 "            \
        "{%0,%1,%2,%3},{%4,%5,%6,%7},{%8,%9},{%0,%1,%2,%3};"                   \
        : "+r"((C4)[0]), "+r"((C4)[1]), "+r"((C4)[2]), "+r"((C4)[3])           \
        : "r"((A4)[0]), "r"((A4)[1]), "r"((A4)[2]), "r"((A4)[3]),              \
          "r"(b0), "r"(b1))

// ---------------------------------------------------------------------------
// fp32 -> bf16 hi/lo split (gate path)
// ---------------------------------------------------------------------------
__global__ void split_kernel(const float4* __restrict__ in,
                             __nv_bfloat162* __restrict__ hi,
                             __nv_bfloat162* __restrict__ lo, int n4)
{
    int i = blockIdx.x * blockDim.x + threadIdx.x;
    if (i >= n4) return;
    float4 a = in[i];
    __nv_bfloat16 hx = __float2bfloat16(a.x);
    __nv_bfloat16 hy = __float2bfloat16(a.y);
    __nv_bfloat16 hz = __float2bfloat16(a.z);
    __nv_bfloat16 hw = __float2bfloat16(a.w);
    float rx = a.x - __bfloat162float(hx);
    float ry = a.y - __bfloat162float(hy);
    float rz = a.z - __bfloat162float(hz);
    float rw = a.w - __bfloat162float(hw);
    hi[2 * i]     = __halves2bfloat162(hx, hy);
    hi[2 * i + 1] = __halves2bfloat162(hz, hw);
    lo[2 * i]     = __halves2bfloat162(__float2bfloat16(rx), __float2bfloat16(ry));
    lo[2 * i + 1] = __halves2bfloat162(__float2bfloat16(rz), __float2bfloat16(rw));
}

// ---------------------------------------------------------------------------
// int8 2-digit quantization, A-side (row-major [M,K], per-row scale), K=2048
// ---------------------------------------------------------------------------
#define QPAIR(v, i1_, i2_) {                                                   \
    float a_ = (v) * inv;                                                      \
    int x1 = __float2int_rn(a_); x1 = max(-127, min(127, x1));                 \
    float e_ = a_ - (float)x1;                                                 \
    int x2 = __float2int_rn(e_ * 254.f); x2 = max(-127, min(127, x2));         \
    i1_ = x1; i2_ = x2; }

__global__ __launch_bounds__(256) void quantA_kernel(
    const float* __restrict__ in, int8_t* __restrict__ q1,
    int8_t* __restrict__ q2, float* __restrict__ sa, int K)
{
    const int m = blockIdx.x;
    const int t = threadIdx.x;
    const int lane = t & 31, wid = t >> 5;
    const float4* rp = (const float4*)(in + (size_t)m * K);
    float4 v0 = rp[2 * t], v1 = rp[2 * t + 1];

    float mx = fmaxf(fmaxf(fmaxf(fabsf(v0.x), fabsf(v0.y)),
                           fmaxf(fabsf(v0.z), fabsf(v0.w))),
                     fmaxf(fmaxf(fabsf(v1.x), fabsf(v1.y)),
                           fmaxf(fabsf(v1.z), fabsf(v1.w))));
#pragma unroll
    for (int off = 16; off > 0; off >>= 1)
        mx = fmaxf(mx, __shfl_xor_sync(0xFFFFFFFFu, mx, off));
    __shared__ float wm[8];
    if (lane == 0) wm[wid] = mx;
    __syncthreads();
    mx = fmaxf(fmaxf(fmaxf(wm[0], wm[1]), fmaxf(wm[2], wm[3])),
               fmaxf(fmaxf(wm[4], wm[5]), fmaxf(wm[6], wm[7])));
    float inv = mx > 0.f ? 127.f / mx : 0.f;
    if (t == 0) sa[m] = mx * (1.f / 127.f);

    int a1[8], a2[8];
    QPAIR(v0.x, a1[0], a2[0]); QPAIR(v0.y, a1[1], a2[1]);
    QPAIR(v0.z, a1[2], a2[2]); QPAIR(v0.w, a1[3], a2[3]);
    QPAIR(v1.x, a1[4], a2[4]); QPAIR(v1.y, a1[5], a2[5]);
    QPAIR(v1.z, a1[6], a2[6]); QPAIR(v1.w, a1[7], a2[7]);

    uint32_t p1a = (a1[0] & 0xFF) | ((a1[1] & 0xFF) << 8) |
                   ((a1[2] & 0xFF) << 16) | ((a1[3] & 0xFF) << 24);
    uint32_t p1b = (a1[4] & 0xFF) | ((a1[5] & 0xFF) << 8) |
                   ((a1[6] & 0xFF) << 16) | ((a1[7] & 0xFF) << 24);
    uint32_t p2a = (a2[0] & 0xFF) | ((a2[1] & 0xFF) << 8) |
                   ((a2[2] & 0xFF) << 16) | ((a2[3] & 0xFF) << 24);
    uint32_t p2b = (a2[4] & 0xFF) | ((a2[5] & 0xFF) << 8) |
                   ((a2[6] & 0xFF) << 16) | ((a2[7] & 0xFF) << 24);
    ((uint2*)(q1 + (size_t)m * K))[t] = make_uint2(p1a, p1b);
    ((uint2*)(q2 + (size_t)m * K))[t] = make_uint2(p2a, p2b);
}

// B-side: column max of [K,N] -> sb[n]
__global__ void colmax_kernel(const float* __restrict__ B,
                              float* __restrict__ sb, int K, int N)
{
    int n = blockIdx.x * blockDim.x + threadIdx.x;
    if (n >= N) return;
    float mx = 0.f;
    for (int k = 0; k < K; k++)
        mx = fmaxf(mx, fabsf(B[(size_t)k * N + n]));
    sb[n] = mx * (1.f / 127.f);
}

// B-side: quantize + transpose [K,N] fp32 -> [N,K] int8 x2 digits.
// grid (K/128, N/32), block 256.
__global__ __launch_bounds__(256) void transq_kernel(
    const float* __restrict__ B, const float* __restrict__ sb,
    int8_t* __restrict__ q1, int8_t* __restrict__ q2, int K, int N)
{
    __shared__ char c1[32][128];
    __shared__ char c2[32][128];
    __shared__ float sinv[32];
    const int k0 = blockIdx.x * 128, n0 = blockIdx.y * 32;
    const int t = threadIdx.x;

    if (t < 32) {
        float s = sb[n0 + t];
        sinv[t] = s > 0.f ? 1.f / s : 0.f;
    }
    __syncthreads();

    const int nl = t & 31, klb = t >> 5;
#pragma unroll
    for (int it = 0; it < 16; it++) {
        int kl = klb + it * 8;
        float inv = sinv[nl];
        float v = B[(size_t)(k0 + kl) * N + n0 + nl];
        int i1, i2;
        QPAIR(v, i1, i2);
        c1[nl][kl] = (char)i1;
        c2[nl][kl] = (char)i2;
    }
    __syncthreads();

    const int n2 = t >> 3, ch = (t & 7) * 16;
    uint4 w1 = *(const uint4*)&c1[n2][ch];
    uint4 w2 = *(const uint4*)&c2[n2][ch];
    *(uint4*)(q1 + (size_t)(n0 + n2) * K + k0 + ch) = w1;
    *(uint4*)(q2 + (size_t)(n0 + n2) * K + k0 + ch) = w2;
}

// ---------------------------------------------------------------------------
// INT8 2-digit batched GEMM via mma.sync.m16n8k32.s8:
//   C = sa[m]*sb[n]*( A1B1 + (A1B2 + A2B1)/254 )
// A [M,K] int8 row-major; B [N,K] int8 row-major (pre-transposed).
// CTA 128x128, K-chunk 64 bytes, 256 threads, 1 CTA/SM, cp.async x2.
// ---------------------------------------------------------------------------
#define ISLOT 10240                        // 128 rows x 80B
#define IOFF_A(buf) ((buf) * 2 * ISLOT)
#define IOFF_B(buf) (4 * ISLOT + (buf) * 2 * ISLOT)
#define IGEMM_SMEM (8 * ISLOT)             // 81920

struct IGemmTriple {
    const int8_t* B1;
    const int8_t* B2;
    const float* sb;
    float* C;
};
struct IGemmBatch {
    const int8_t* A1;
    const int8_t* A2;
    const float* sa;
    IGemmTriple t[4];
};

__device__ __forceinline__ void igemm_load(
    uint32_t sbm, int buf,
    const int8_t* __restrict__ A1, const int8_t* __restrict__ A2,
    const int8_t* __restrict__ B1, const int8_t* __restrict__ B2,
    int m0, int n0, int k0, int K, int tid)
{
#pragma unroll
    for (int r = 0; r < 2; r++) {
        int i = tid + (r << 8);
        int row = i >> 2;
        int kc = (i & 3) << 4;
        uint32_t dA = sbm + IOFF_A(buf) + row * 80 + kc;
        CP16(dA,         (const void*)(A1 + (size_t)(m0 + row) * K + k0 + kc));
        CP16(dA + ISLOT, (const void*)(A2 + (size_t)(m0 + row) * K + k0 + kc));
        uint32_t dB = sbm + IOFF_B(buf) + row * 80 + kc;
        CP16(dB,         (const void*)(B1 + (size_t)(n0 + row) * K + k0 + kc));
        CP16(dB + ISLOT, (const void*)(B2 + (size_t)(n0 + row) * K + k0 + kc));
    }
}

__global__ void __launch_bounds__(256, 1)
igemm_kernel(IGemmBatch gb, int M, int N, int K)
{
    extern __shared__ char smem[];
    const uint32_t sbm = smem_u32(smem);
    const int tid  = threadIdx.x;
    const int lane = tid & 31;
    const int wid  = tid >> 5;
    const int wm0  = (wid >> 2) * 64;
    const int wn0  = (wid & 3) * 32;
    const int m0 = blockIdx.y * 128;
    const int n0 = blockIdx.x * 128;

    const int8_t* __restrict__ A1 = gb.A1;
    const int8_t* __restrict__ A2 = gb.A2;
    const int8_t* __restrict__ B1 = gb.t[blockIdx.z].B1;
    const int8_t* __restrict__ B2 = gb.t[blockIdx.z].B2;
    const float* __restrict__ sav = gb.sa;
    const float* __restrict__ sbv = gb.t[blockIdx.z].sb;
    float* __restrict__ C = gb.t[blockIdx.z].C;

    int accM[4][4][4], accX[4][4][4];
#pragma unroll
    for (int a = 0; a < 4; a++)
#pragma unroll
        for (int b = 0; b < 4; b++)
#pragma unroll
            for (int c = 0; c < 4; c++) { accM[a][b][c] = 0; accX[a][b][c] = 0; }

    const int nch = K >> 6;   // 64-byte chunks

    igemm_load(sbm, 0, A1, A2, B1, B2, m0, n0, 0, K, tid);
    CP_COMMIT();

    for (int ch = 0; ch < nch; ch++) {
        const int buf = ch & 1;
        if (ch + 1 < nch) {
            igemm_load(sbm, buf ^ 1, A1, A2, B1, B2, m0, n0, (ch + 1) << 6, K, tid);
            CP_COMMIT();
            CP_WAIT1();
        } else {
            CP_WAIT0();
        }
        __syncthreads();

        const uint32_t aBase = sbm + IOFF_A(buf);
        const uint32_t bBase = sbm + IOFF_B(buf);

#pragma unroll
        for (int kk = 0; kk < 2; kk++) {
            const uint32_t kb = kk * 32 + ((lane >> 4) << 4);
            uint32_t Af[4][4], B1f[2][4], B2f[2][4];

            // B fragments (both digits): rows = n, non-trans ldmatrix
#pragma unroll
            for (int nh = 0; nh < 2; nh++) {
                uint32_t bd = bBase + (uint32_t)(wn0 + nh * 16 + (lane & 15)) * 80 + kb;
                LDSM4(B1f[nh], bd);
                LDSM4(B2f[nh], bd + ISLOT);
            }
            // A digit-1 fragments
#pragma unroll
            for (int mb = 0; mb < 4; mb++) {
                uint32_t ad = aBase + (uint32_t)(wm0 + mb * 16 + (lane & 15)) * 80 + kb;
                LDSM4(Af[mb], ad);
            }
            // passes 1+2: A1*B1 -> main, A1*B2 -> cross
#pragma unroll
            for (int mb = 0; mb < 4; mb++) {
#pragma unroll
                for (int nb = 0; nb < 4; nb++) {
                    const int nh = nb >> 1, lo = nb & 1;
                    IMMA16832(accM[mb][nb], Af[mb], B1f[nh][lo], B1f[nh][lo + 2]);
                    IMMA16832(accX[mb][nb], Af[mb], B2f[nh][lo], B2f[nh][lo + 2]);
                }
            }
            // A digit-2 fragments (reuse regs)
#pragma unroll
            for (int mb = 0; mb < 4; mb++) {
                uint32_t ad = aBase + ISLOT
                            + (uint32_t)(wm0 + mb * 16 + (lane & 15)) * 80 + kb;
                LDSM4(Af[mb], ad);
            }
            // pass 3: A2*B1 -> cross
#pragma unroll
            for (int mb = 0; mb < 4; mb++) {
#pragma unroll
                for (int nb = 0; nb < 4; nb++) {
                    const int nh = nb >> 1, lo = nb & 1;
                    IMMA16832(accX[mb][nb], Af[mb], B1f[nh][lo], B1f[nh][lo + 2]);
                }
            }
        }
        __syncthreads();
    }

    // dequant epilogue
    const float inv254 = 1.f / 254.f;
#pragma unroll
    for (int mb = 0; mb < 4; mb++) {
        int rr = m0 + wm0 + mb * 16 + (lane >> 2);
        float s0 = sav[rr], s1 = sav[rr + 8];
#pragma unroll
        for (int nb = 0; nb < 4; nb++) {
            int cc = n0 + wn0 + nb * 8 + ((lane & 3) << 1);
            float t0 = sbv[cc], t1 = sbv[cc + 1];
            const int* Mv = accM[mb][nb];
            const int* Xv = accX[mb][nb];
            float2 v0 = make_float2(((float)Mv[0] + (float)Xv[0] * inv254) * (s0 * t0),
                                    ((float)Mv[1] + (float)Xv[1] * inv254) * (s0 * t1));
            float2 v1 = make_float2(((float)Mv[2] + (float)Xv[2] * inv254) * (s1 * t0),
                                    ((float)Mv[3] + (float)Xv[3] * inv254) * (s1 * t1));
            *(float2*)&C[(size_t)rr * N + cc]       = v0;
            *(float2*)&C[(size_t)(rr + 8) * N + cc] = v1;
        }
    }
}

// ---------------------------------------------------------------------------
// bf16-split tensor GEMM (gate path: f1, f2). Same as R9.
// ---------------------------------------------------------------------------
#define BKC 32
#define A_STR 40
#define B_STR 136
#define SA_SLOT (128 * A_STR * 2)
#define SB_SLOT (BKC * B_STR * 2)
#define ABYTES (4 * SA_SLOT)
#define OFF_A(buf, hl) ((buf) * 2 * SA_SLOT + (hl) * SA_SLOT)
#define OFF_B(buf, hl) (ABYTES + (buf) * 2 * SB_SLOT + (hl) * SB_SLOT)
#define GEMM_SMEM (ABYTES + 4 * SB_SLOT)

__device__ __forceinline__ void gemm_load_chunk(
    uint32_t sb, int buf,
    const __nv_bfloat16* __restrict__ Ah, const __nv_bfloat16* __restrict__ Al,
    const __nv_bfloat16* __restrict__ Bh, const __nv_bfloat16* __restrict__ Bl,
    int m0, int n0, int k0, int K, int N, int tid)
{
#pragma unroll
    for (int r = 0; r < 2; r++) {
        int i = tid + (r << 8);
        int row = i >> 2;
        int kc  = (i & 3) << 3;
        uint32_t da = sb + OFF_A(buf, 0) + row * (A_STR * 2) + kc * 2;
        CP16(da, (const void*)(Ah + (size_t)(m0 + row) * K + k0 + kc));
        CP16(da + SA_SLOT, (const void*)(Al + (size_t)(m0 + row) * K + k0 + kc));
    }
#pragma unroll
    for (int r = 0; r < 2; r++) {
        int i = tid + (r << 8);
        int krow = i >> 4;
        int nc   = (i & 15) << 3;
        uint32_t db = sb + OFF_B(buf, 0) + krow * (B_STR * 2) + nc * 2;
        CP16(db, (const void*)(Bh + (size_t)(k0 + krow) * N + n0 + nc));
        CP16(db + SB_SLOT, (const void*)(Bl + (size_t)(k0 + krow) * N + n0 + nc));
    }
}

__global__ void __launch_bounds__(256, 2)
tgemm_kernel(const __nv_bfloat16* __restrict__ Ah,
             const __nv_bfloat16* __restrict__ Al,
             const __nv_bfloat16* __restrict__ Bh,
             const __nv_bfloat16* __restrict__ Bl,
             float* __restrict__ C, int M, int N, int K)
{
    extern __shared__ char smem[];
    const uint32_t sb = smem_u32(smem);
    const int tid  = threadIdx.x;
    const int lane = tid & 31;
    const int wid  = tid >> 5;
    const int wm0  = (wid >> 2) * 64;
    const int wn0  = (wid & 3) * 32;
    const int m0 = blockIdx.y * 128;
    const int n0 = blockIdx.x * 128;

    float acc[4][4][4];
#pragma unroll
    for (int a = 0; a < 4; a++)
#pragma unroll
        for (int b = 0; b < 4; b++)
#pragma unroll
            for (int c = 0; c < 4; c++) acc[a][b][c] = 0.f;

    const int nch = K / BKC;
    gemm_load_chunk(sb, 0, Ah, Al, Bh, Bl, m0, n0, 0, K, N, tid);
    CP_COMMIT();

    for (int ch = 0; ch < nch; ch++) {
        const int buf = ch & 1;
        if (ch + 1 < nch) {
            gemm_load_chunk(sb, buf ^ 1, Ah, Al, Bh, Bl,
                            m0, n0, (ch + 1) * BKC, K, N, tid);
            CP_COMMIT();
            CP_WAIT1();
        } else {
            CP_WAIT0();
        }
        __syncthreads();

        const uint32_t aBase = sb + OFF_A(buf, 0);
        const uint32_t bBase = sb + OFF_B(buf, 0);

#pragma unroll
        for (int kk = 0; kk < 2; kk++) {
            const int kb = kk * 16;
            uint32_t Af[4][4], Bhf[2][4], Blf[2][4];
            const int arow = wm0 + (lane & 15);
            const uint32_t kcol = (uint32_t)(kb + ((lane >> 4) << 3)) * 2;
            const int krow = kb + (lane & 15);

#pragma unroll
            for (int nb2 = 0; nb2 < 2; nb2++) {
                uint32_t nby = (uint32_t)(wn0 + nb2 * 16 + ((lane >> 4) << 3)) * 2;
                uint32_t bd = bBase + (uint32_t)krow * (B_STR * 2) + nby;
                LDSM4T(Bhf[nb2], bd);
                LDSM4T(Blf[nb2], bd + SB_SLOT);
            }
#pragma unroll
            for (int mb = 0; mb < 4; mb++) {
                uint32_t ad = aBase + (uint32_t)(arow + mb * 16) * (A_STR * 2) + kcol;
                LDSM4(Af[mb], ad);
            }
#pragma unroll
            for (int mb = 0; mb < 4; mb++) {
#pragma unroll
                for (int nb = 0; nb < 4; nb++) {
                    uint32_t bh0 = Bhf[nb >> 1][(nb & 1) << 1];
                    uint32_t bh1 = Bhf[nb >> 1][((nb & 1) << 1) | 1];
                    uint32_t bl0 = Blf[nb >> 1][(nb & 1) << 1];
                    uint32_t bl1 = Blf[nb >> 1][((nb & 1) << 1) | 1];
                    MMA16816(acc[mb][nb], Af[mb], bh0, bh1);
                    MMA16816(acc[mb][nb], Af[mb], bl0, bl1);
                }
            }
#pragma unroll
            for (int mb = 0; mb < 4; mb++) {
                uint32_t ad = aBase + SA_SLOT
                            + (uint32_t)(arow + mb * 16) * (A_STR * 2) + kcol;
                LDSM4(Af[mb], ad);
            }
#pragma unroll
            for (int mb = 0; mb < 4; mb++) {
#pragma unroll
                for (int nb = 0; nb < 4; nb++) {
                    uint32_t bh0 = Bhf[nb >> 1][(nb & 1) << 1];
                    uint32_t bh1 = Bhf[nb >> 1][((nb & 1) << 1) | 1];
                    MMA16816(acc[mb][nb], Af[mb], bh0, bh1);
                }
            }
        }
        __syncthreads();
    }

#pragma unroll
    for (int mb = 0; mb < 4; mb++) {
#pragma unroll
        for (int nb = 0; nb < 4; nb++) {
            int r = m0 + wm0 + mb * 16 + (lane >> 2);
            int c = n0 + wn0 + nb * 8 + ((lane & 3) << 1);
            float2 v0 = make_float2(acc[mb][nb][0], acc[mb][nb][1]);
            float2 v1 = make_float2(acc[mb][nb][2], acc[mb][nb][3]);
            *(float2*)&C[(size_t)r * N + c]       = v0;
            *(float2*)&C[(size_t)(r + 8) * N + c] = v1;
        }
    }
}

// ---------------------------------------------------------------------------
// beta = sigmoid(x @ Wb)
// ---------------------------------------------------------------------------
__global__ __launch_bounds__(128) void beta_kernel(
    const float* __restrict__ x, const float* __restrict__ Wb,
    float* __restrict__ beta)
{
    const int m = blockIdx.x;
    const int tid = threadIdx.x;
    const float* xr = x + (size_t)m * DIM;

    float acc[NH];
#pragma unroll
    for (int h = 0; h < NH; h++) acc[h] = 0.f;

    for (int k = tid; k < DIM; k += 128) {
        float xv = xr[k];
        const float* wr = Wb + (size_t)k * NH;
#pragma unroll
        for (int h = 0; h < NH; h++) acc[h] += xv * wr[h];
    }

    __shared__ float sh[128 * NH];
#pragma unroll
    for (int h = 0; h < NH; h++) sh[tid * NH + h] = acc[h];
    __syncthreads();

    if (tid < NH) {
        float s = 0.f;
        for (int i = 0; i < 128; i++) s += sh[i * NH + tid];
        beta[(size_t)m * NH + tid] = 1.f / (1.f + expf(-s));
    }
}

// ---------------------------------------------------------------------------
// Causal depthwise conv (K=4) + SiLU (+ per-head L2 norm)
// ---------------------------------------------------------------------------
template <bool NORM>
__global__ __launch_bounds__(128) void conv_kernel(
    const float* __restrict__ xin, const float* __restrict__ w,
    float* __restrict__ out)
{
    const int TT = 32;
    const int t0 = blockIdx.x * TT;
    const int c0 = blockIdx.y * 128;
    const int b  = blockIdx.z;
    const int tid = threadIdx.x;
    const int c = c0 + tid;

    __shared__ float xsh[TT + 3][128];
    __shared__ float ysh[TT][128];
    __shared__ float rns[TT];

    const float* xb = xin + ((size_t)b * SEQ) * DIM + c;
#pragma unroll
    for (int r = 0; r < TT + 3; r++) {
        int t = t0 - 3 + r;
        xsh[r][tid] = (t >= 0) ? xb[(size_t)t * DIM] : 0.f;
    }
    float4 wv = *(const float4*)(w + (size_t)c * 4);
    __syncthreads();

    float yreg[TT];
#pragma unroll
    for (int tt = 0; tt < TT; tt++) {
        float y = xsh[tt][tid] * wv.x + xsh[tt + 1][tid] * wv.y
                + xsh[tt + 2][tid] * wv.z + xsh[tt + 3][tid] * wv.w;
        y = y / (1.f + expf(-y));
        yreg[tt] = y;
        if (NORM) ysh[tt][tid] = y;
    }

    if (NORM) {
        __syncthreads();
        const int wd = tid >> 5, lane = tid & 31;
        for (int tt = wd; tt < TT; tt += 4) {
            float a0 = ysh[tt][lane],      a1 = ysh[tt][lane + 32];
            float a2 = ysh[tt][lane + 64], a3 = ysh[tt][lane + 96];
            float s = a0 * a0 + a1 * a1 + a2 * a2 + a3 * a3;
#pragma unroll
            for (int off = 16; off > 0; off >>= 1)
                s += __shfl_xor_sync(0xFFFFFFFFu, s, off);
            if (lane == 0) rns[tt] = rsqrtf(s + 1e-6f);
        }
        __syncthreads();
    }

    float* ob = out + ((size_t)b * SEQ) * DIM + c;
#pragma unroll
    for (int tt = 0; tt < TT; tt++) {
        float y = yreg[tt];
        if (NORM) y *= rns[tt];
        ob[(size_t)(t0 + tt) * DIM] = y;
    }
}

// ---------------------------------------------------------------------------
// gexp
// ---------------------------------------------------------------------------
__global__ void gexp_kernel(float* __restrict__ g,
                            const float* __restrict__ A_log,
                            const float* __restrict__ dt_bias, int n)
{
    int i = blockIdx.x * blockDim.x + threadIdx.x;
    if (i >= n) return;
    int c = i & (DIM - 1);
    int h = c >> 7;
    float a = -expf(A_log[h]);
    float u = g[i] + dt_bias[c];
    float sp = (u > 20.f) ? u : log1pf(expf(u));
    g[i] = expf(a * sp);
}

// ---------------------------------------------------------------------------
// Delta-rule scan, barrier-free (as R9).
// ---------------------------------------------------------------------------
#define SCAN_LOAD(J, qb_, kb_, gb_, vt_, bt_, tt)                              \
    do {                                                                       \
        const float4* _qp = qp + (size_t)(tt) * ST4;                           \
        const float4* _kp = kp + (size_t)(tt) * ST4;                           \
        const float4* _gp = gp + (size_t)(tt) * ST4;                           \
        _Pragma("unroll")                                                      \
        for (int j = 0; j < 4; j++) {                                          \
            qb_[j] = _qp[j]; kb_[j] = _kp[j]; gb_[j] = _gp[j];                 \
        }                                                                      \
        vt_ = v[vbase + (size_t)(tt) * (NH * DV)];                             \
        bt_ = beta[bbase + (size_t)(tt) * NH];                                 \
    } while (0)

#define SCAN_STEP(qb_, kb_, gb_, vt_, bt_, tt)                                 \
    do {                                                                       \
        float kv0 = 0.f, kv1 = 0.f, kv2 = 0.f, kv3 = 0.f;                      \
        _Pragma("unroll")                                                      \
        for (int ii = 0; ii < 4; ii++) {                                       \
            float4 kk4 = kb_[ii]; float4 gg4 = gb_[ii];                        \
            S[4*ii+0] *= gg4.x; kv0 += kk4.x * S[4*ii+0];                      \
            S[4*ii+1] *= gg4.y; kv1 += kk4.y * S[4*ii+1];                      \
            S[4*ii+2] *= gg4.z; kv2 += kk4.z * S[4*ii+2];                      \
            S[4*ii+3] *= gg4.w; kv3 += kk4.w * S[4*ii+3];                      \
        }                                                                      \
        float kv = (kv0 + kv1) + (kv2 + kv3);                                  \
        kv += __shfl_xor_sync(0xFFFFFFFFu, kv, 1);                             \
        kv += __shfl_xor_sync(0xFFFFFFFFu, kv, 2);                             \
        kv += __shfl_xor_sync(0xFFFFFFFFu, kv, 4);                             \
        float upd = (vt_ - kv) * bt_;                                          \
        float ov0 = 0.f, ov1 = 0.f, ov2 = 0.f, ov3 = 0.f;                      \
        _Pragma("unroll")                                                      \
        for (int ii = 0; ii < 4; ii++) {                                       \
            float4 kk4 = kb_[ii]; float4 qq4 = qb_[ii];                        \
            S[4*ii+0] += kk4.x * upd; ov0 += qq4.x * S[4*ii+0];                \
            S[4*ii+1] += kk4.y * upd; ov1 += qq4.y * S[4*ii+1];                \
            S[4*ii+2] += kk4.z * upd; ov2 += qq4.z * S[4*ii+2];                \
            S[4*ii+3] += kk4.w * upd; ov3 += qq4.w * S[4*ii+3];                \
        }                                                                      \
        float ov = (ov0 + ov1) + (ov2 + ov3);                                  \
        ov += __shfl_xor_sync(0xFFFFFFFFu, ov, 1);                             \
        ov += __shfl_xor_sync(0xFFFFFFFFu, ov, 2);                             \
        ov += __shfl_xor_sync(0xFFFFFFFFu, ov, 4);                             \
        if (s == 0) o[vbase + (size_t)(tt) * (NH * DV)] = ov * scale;          \
    } while (0)

__global__ __launch_bounds__(256) void scan_kernel(
    const float* __restrict__ q, const float* __restrict__ k,
    const float* __restrict__ v, const float* __restrict__ ge,
    const float* __restrict__ beta, float* __restrict__ o)
{
    const int bh = blockIdx.x >> 2;
    const int cg = blockIdx.x & 3;
    const int b  = bh / NH, h = bh % NH;
    const int tid = threadIdx.x;
    const int s   = tid & 7;
    const int col = cg * 32 + (tid >> 3);

    const float scale = 0.08838834764831845f;
    const size_t kbase = ((size_t)(b * SEQ) * NH + h) * (size_t)DK + s * 16;
    const size_t vbase = ((size_t)(b * SEQ) * NH + h) * (size_t)DV + col;
    const size_t bbase = (size_t)(b * SEQ) * NH + h;
    const int ST4 = (NH * DK) / 4;

    const float4* qp = (const float4*)(q + kbase);
    const float4* kp = (const float4*)(k + kbase);
    const float4* gp = (const float4*)(ge + kbase);

    float S[16];
#pragma unroll
    for (int i = 0; i < 16; i++) S[i] = 0.f;

    float4 q0[4], k0[4], g0[4], q1[4], k1[4], g1[4];
    float vt0, bt0, vt1, bt1;

    SCAN_LOAD(0, q0, k0, g0, vt0, bt0, 0);

    for (int t = 0; t < SEQ; t += 2) {
        SCAN_LOAD(1, q1, k1, g1, vt1, bt1, t + 1);
        SCAN_STEP(q0, k0, g0, vt0, bt0, t);
        if (t + 2 < SEQ)
            SCAN_LOAD(0, q0, k0, g0, vt0, bt0, t + 2);
        SCAN_STEP(q1, k1, g1, vt1, bt1, t + 1);
    }
}

// ---------------------------------------------------------------------------
// Epilogue: gated RMSNorm -> fp32 buffer (quantized afterwards)
// ---------------------------------------------------------------------------
__global__ __launch_bounds__(128) void epilogue_kernel(
    const float* __restrict__ o, const float* __restrict__ gate,
    const float* __restrict__ bg, const float* __restrict__ onw,
    float* __restrict__ on)
{
    const int m = blockIdx.x;
    const int h = blockIdx.y;
    const int tid = threadIdx.x;
    size_t idx = ((size_t)m * NH + h) * (size_t)DV + tid;

    float ov = o[idx];
    float s = ov * ov;
#pragma unroll
    for (int off = 16; off > 0; off >>= 1)
        s += __shfl_xor_sync(0xFFFFFFFFu, s, off);

    __shared__ float ws[4];
    const int wd = tid >> 5, lane = tid & 31;
    if (lane == 0) ws[wd] = s;
    __syncthreads();
    float tot = ws[0] + ws[1] + ws[2] + ws[3];

    float r = rsqrtf(tot * (1.f / 128.f) + 1e-5f);
    float gv = gate[idx] + bg[h * DV + tid];
    float sig = 1.f / (1.f + expf(-gv));
    on[idx] = ov * r * onw[tid] * (gv * sig);
}

// ---------------------------------------------------------------------------
// kernel_launch
// ---------------------------------------------------------------------------
static inline void do_split(const float* src, __nv_bfloat16* hi,
                            __nv_bfloat16* lo, int n)
{
    int n4 = n >> 2;
    split_kernel<<<(n4 + 255) / 256, 256>>>(
        (const float4*)src, (__nv_bfloat162*)hi, (__nv_bfloat162*)lo, n4);
}

static inline void do_quantB(const float* W, float* sb, int8_t* q1, int8_t* q2,
                             int K, int N)
{
    colmax_kernel<<<(N + 255) / 256, 256>>>(W, sb, K, N);
    dim3 g(K / 128, N / 32);
    transq_kernel<<<g, 256>>>(W, sb, q1, q2, K, N);
}

extern "C" void kernel_launch(void* const* d_in, const int* in_sizes, int n_in,
                              void* d_out, int out_size)
{
    const float* x       = (const float*)d_in[0];
    const float* Wq      = (const float*)d_in[1];
    const float* Wk      = (const float*)d_in[2];
    const float* Wv      = (const float*)d_in[3];
    const float* conv_q  = (const float*)d_in[4];
    const float* conv_k  = (const float*)d_in[5];
    const float* conv_v  = (const float*)d_in[6];
    const float* Wf1     = (const float*)d_in[7];
    const float* Wf2     = (const float*)d_in[8];
    const float* Wb      = (const float*)d_in[9];
    const float* A_log   = (const float*)d_in[10];
    const float* dt_bias = (const float*)d_in[11];
    const float* Wg      = (const float*)d_in[12];
    const float* bg      = (const float*)d_in[13];
    const float* o_norm_w= (const float*)d_in[14];
    const float* Wo      = (const float*)d_in[15];
    float* out = (float*)d_out;

    cudaFuncSetAttribute(tgemm_kernel,
                         cudaFuncAttributeMaxDynamicSharedMemorySize, GEMM_SMEM);
    cudaFuncSetAttribute(igemm_kernel,
                         cudaFuncAttributeMaxDynamicSharedMemorySize, IGEMM_SMEM);

    float *qpre, *kpre, *vpre, *qb, *kb, *vb, *gateb, *gb, *ob, *f1b, *betab;
    cudaGetSymbolAddress((void**)&qpre,  g_qpre);
    cudaGetSymbolAddress((void**)&kpre,  g_kpre);
    cudaGetSymbolAddress((void**)&vpre,  g_vpre);
    cudaGetSymbolAddress((void**)&qb,    g_q);
    cudaGetSymbolAddress((void**)&kb,    g_k);
    cudaGetSymbolAddress((void**)&vb,    g_v);
    cudaGetSymbolAddress((void**)&gateb, g_gate);
    cudaGetSymbolAddress((void**)&gb,    g_g);
    cudaGetSymbolAddress((void**)&ob,    g_o);
    cudaGetSymbolAddress((void**)&f1b,   g_f1);
    cudaGetSymbolAddress((void**)&betab, g_beta);

    __nv_bfloat16 *xh, *xl, *wf1h, *wf1l, *wf2h, *wf2l, *f1h, *f1l;
    cudaGetSymbolAddress((void**)&xh,   g_xh);   cudaGetSymbolAddress((void**)&xl,   g_xl);
    cudaGetSymbolAddress((void**)&wf1h, g_wf1h); cudaGetSymbolAddress((void**)&wf1l, g_wf1l);
    cudaGetSymbolAddress((void**)&wf2h, g_wf2h); cudaGetSymbolAddress((void**)&wf2l, g_wf2l);
    cudaGetSymbolAddress((void**)&f1h,  g_f1h);  cudaGetSymbolAddress((void**)&f1l,  g_f1l);

    int8_t *xq1, *xq2, *oq1, *oq2;
    int8_t *q1wq, *q2wq, *q1wk, *q2wk, *q1wv, *q2wv, *q1wg, *q2wg, *q1wo, *q2wo;
    float *saX, *saO, *sbq, *sbk, *sbv_, *sbg, *sbo;
    cudaGetSymbolAddress((void**)&xq1, g_xq1);  cudaGetSymbolAddress((void**)&xq2, g_xq2);
    cudaGetSymbolAddress((void**)&oq1, g_oq1);  cudaGetSymbolAddress((void**)&oq2, g_oq2);
    cudaGetSymbolAddress((void**)&q1wq, g_q1wq); cudaGetSymbolAddress((void**)&q2wq, g_q2wq);
    cudaGetSymbolAddress((void**)&q1wk, g_q1wk); cudaGetSymbolAddress((void**)&q2wk, g_q2wk);
    cudaGetSymbolAddress((void**)&q1wv, g_q1wv); cudaGetSymbolAddress((void**)&q2wv, g_q2wv);
    cudaGetSymbolAddress((void**)&q1wg, g_q1wg); cudaGetSymbolAddress((void**)&q2wg, g_q2wg);
    cudaGetSymbolAddress((void**)&q1wo, g_q1wo); cudaGetSymbolAddress((void**)&q2wo, g_q2wo);
    cudaGetSymbolAddress((void**)&saX, g_saX);  cudaGetSymbolAddress((void**)&saO, g_saO);
    cudaGetSymbolAddress((void**)&sbq, g_sbq);  cudaGetSymbolAddress((void**)&sbk, g_sbk);
    cudaGetSymbolAddress((void**)&sbv_, g_sbv); cudaGetSymbolAddress((void**)&sbg, g_sbg);
    cudaGetSymbolAddress((void**)&sbo, g_sbo);

    // --- int8 quantization of x and the 5 big weights ---
    quantA_kernel<<<MTOT, 256>>>(x, xq1, xq2, saX, DIM);
    do_quantB(Wq, sbq, q1wq, q2wq, DIM, DIM);
    do_quantB(Wk, sbk, q1wk, q2wk, DIM, DIM);
    do_quantB(Wv, sbv_, q1wv, q2wv, DIM, DIM);
    do_quantB(Wg, sbg, q1wg, q2wg, DIM, DIM);
    do_quantB(Wo, sbo, q1wo, q2wo, DIM, DIM);

    // --- batched QKVG projection, int8 tensor cores ---
    {
        IGemmBatch gbat;
        gbat.A1 = xq1; gbat.A2 = xq2; gbat.sa = saX;
        gbat.t[0] = { q1wq, q2wq, sbq, qpre };
        gbat.t[1] = { q1wk, q2wk, sbk, kpre };
        gbat.t[2] = { q1wv, q2wv, sbv_, vpre };
        gbat.t[3] = { q1wg, q2wg, sbg, gateb };
        dim3 g(DIM / 128, MTOT / 128, 4);
        igemm_kernel<<<g, 256, IGEMM_SMEM>>>(gbat, MTOT, DIM, DIM);
    }

    // --- gate path (bf16 3-pass, precision-critical) ---
    do_split(x,   xh,   xl,   NELEM);
    do_split(Wf1, wf1h, wf1l, DIM * DV);
    do_split(Wf2, wf2h, wf2l, DV * DIM);
    {
        dim3 g(DV / 128, MTOT / 128, 1);
        tgemm_kernel<<<g, 256, GEMM_SMEM>>>(xh, xl, wf1h, wf1l, f1b, MTOT, DV, DIM);
    }
    do_split(f1b, f1h, f1l, MTOT * DV);
    {
        dim3 g(DIM / 128, MTOT / 128, 1);
        tgemm_kernel<<<g, 256, GEMM_SMEM>>>(f1h, f1l, wf2h, wf2l, gb, MTOT, DIM, DV);
    }

    beta_kernel<<<MTOT, 128>>>(x, Wb, betab);

    // --- conv + silu (+ l2norm for q,k) ---
    dim3 gConv(SEQ / 32, DIM / 128, BATCH);
    conv_kernel<true ><<<gConv, 128>>>(qpre, conv_q, qb);
    conv_kernel<true ><<<gConv, 128>>>(kpre, conv_k, kb);
    conv_kernel<false><<<gConv, 128>>>(vpre, conv_v, vb);

    // --- decay gates ---
    gexp_kernel<<<NELEM / 256, 256>>>(gb, A_log, dt_bias, NELEM);

    // --- delta-rule scan ---
    scan_kernel<<<BATCH * NH * 4, 256>>>(qb, kb, vb, gb, betab, ob);

    // --- gated RMSNorm epilogue (fp32 out into qpre, now free) ---
    dim3 gEpi(MTOT, NH);
    epilogue_kernel<<<gEpi, 128>>>(ob, gateb, bg, o_norm_w, qpre);

    // --- output projection, int8 ---
    quantA_kernel<<<MTOT, 256>>>(qpre, oq1, oq2, saO, DIM);
    {
        IGemmBatch gbat;
        gbat.A1 = oq1; gbat.A2 = oq2; gbat.sa = saO;
        gbat.t[0] = { q1wo, q2wo, sbo, out };
        gbat.t[1] = gbat.t[0]; gbat.t[2] = gbat.t[0]; gbat.t[3] = gbat.t[0];
        dim3 g(DIM / 128, MTOT / 128, 1);
        igemm_kernel<<<g, 256, IGEMM_SMEM>>>(gbat, MTOT, DIM, DIM);
    }
}

// round 11
// speedup vs baseline: 2.1319x; 2.1319x over previous
#include <cuda_runtime.h>
#include <cuda_bf16.h>
#include <cuda_fp16.h>
#include <math.h>
#include <stdint.h>

// ---------------------------------------------------------------------------
// Problem constants
// ---------------------------------------------------------------------------
#define BATCH 2
#define SEQ   2048
#define DIM   2048
#define NH    16
#define DK    128
#define DV    128
#define MTOT  (BATCH * SEQ)          // 4096
#define NELEM (MTOT * DIM)           // 8388608
#define WSZ   (DIM * DIM)            // 4194304

// ---------------------------------------------------------------------------
// Device scratch
// ---------------------------------------------------------------------------
__device__ float g_qpre[NELEM];          // also reused as normalized-o buffer
__device__ float g_kpre[NELEM];
__device__ float g_vpre[NELEM];
__device__ float g_q[NELEM];
__device__ float g_k[NELEM];
__device__ float g_v[NELEM];
__device__ float g_gate[NELEM];
__device__ float g_g[NELEM];
__device__ float g_o[NELEM];
__device__ float g_f1[MTOT * DV];
__device__ float g_beta[MTOT * NH];

// bf16 split buffers (gate path only: x, Wf1, Wf2, f1)
__device__ __nv_bfloat16 g_xbh[NELEM],  g_xbl[NELEM];
__device__ __nv_bfloat16 g_wf1h[DIM*DV], g_wf1l[DIM*DV];
__device__ __nv_bfloat16 g_wf2h[DV*DIM], g_wf2l[DV*DIM];
__device__ __nv_bfloat16 g_f1h[MTOT*DV], g_f1l[MTOT*DV];

// fp16 buffers (main GEMM path)
__device__ __half g_xhh[NELEM], g_xhl[NELEM];      // x hi/lo split
__device__ __half g_ohh[NELEM], g_ohl[NELEM];      // normalized-o hi/lo split
__device__ __half g_hwq[WSZ], g_hwk[WSZ], g_hwv[WSZ], g_hwg[WSZ], g_hwo[WSZ];

// ---------------------------------------------------------------------------
// PTX helpers (baseline ISA: mma.sync / ldmatrix / cp.async)
// ---------------------------------------------------------------------------
__device__ __forceinline__ uint32_t smem_u32(const void* p) {
    uint32_t a;
    asm("{ .reg .u64 t; cvta.to.shared.u64 t, %1; cvt.u32.u64 %0, t; }"
        : "=r"(a) : "l"(p));
    return a;
}

#define CP16(dst, src) \
    asm volatile("cp.async.cg.shared.global [%0], [%1], 16;" \
                 :: "r"(dst), "l"(src))
#define CP_COMMIT() asm volatile("cp.async.commit_group;" ::: "memory")
#define CP_WAIT0()  asm volatile("cp.async.wait_group 0;" ::: "memory")
#define CP_WAIT1()  asm volatile("cp.async.wait_group 1;" ::: "memory")

#define LDSM4(R, addr)                                                         \
    asm volatile("ldmatrix.sync.aligned.m8n8.x4.shared.b16 {%0,%1,%2,%3}, [%4];" \
        : "=r"((R)[0]), "=r"((R)[1]), "=r"((R)[2]), "=r"((R)[3]) : "r"(addr))

#define LDSM4T(R, addr)                                                        \
    asm volatile("ldmatrix.sync.aligned.m8n8.x4.trans.shared.b16 {%0,%1,%2,%3}, [%4];" \
        : "=r"((R)[0]), "=r"((R)[1]), "=r"((R)[2]), "=r"((R)[3]) : "r"(addr))

#define MMA_BF16(C4, A4, b0, b1)                                               \
    asm volatile("mma.sync.aligned.m16n8k16.row.col.f32.bf16.bf16.f32 "        \
        "{%0,%1,%2,%3},{%4,%5,%6,%7},{%8,%9},{%0,%1,%2,%3};"                   \
        : "+f"((C4)[0]), "+f"((C4)[1]), "+f"((C4)[2]), "+f"((C4)[3])           \
        : "r"((A4)[0]), "r"((A4)[1]), "r"((A4)[2]), "r"((A4)[3]),              \
          "r"(b0), "r"(b1))

#define MMA_F16(C4, A4, b0, b1)                                                \
    asm volatile("mma.sync.aligned.m16n8k16.row.col.f32.f16.f16.f32 "          \
        "{%0,%1,%2,%3},{%4,%5,%6,%7},{%8,%9},{%0,%1,%2,%3};"                   \
        : "+f"((C4)[0]), "+f"((C4)[1]), "+f"((C4)[2]), "+f"((C4)[3])           \
        : "r"((A4)[0]), "r"((A4)[1]), "r"((A4)[2]), "r"((A4)[3]),              \
          "r"(b0), "r"(b1))

// ---------------------------------------------------------------------------
// fp32 -> bf16 hi/lo split (gate path)
// ---------------------------------------------------------------------------
__global__ void split_kernel(const float4* __restrict__ in,
                             __nv_bfloat162* __restrict__ hi,
                             __nv_bfloat162* __restrict__ lo, int n4)
{
    int i = blockIdx.x * blockDim.x + threadIdx.x;
    if (i >= n4) return;
    float4 a = in[i];
    __nv_bfloat16 hx = __float2bfloat16(a.x);
    __nv_bfloat16 hy = __float2bfloat16(a.y);
    __nv_bfloat16 hz = __float2bfloat16(a.z);
    __nv_bfloat16 hw = __float2bfloat16(a.w);
    float rx = a.x - __bfloat162float(hx);
    float ry = a.y - __bfloat162float(hy);
    float rz = a.z - __bfloat162float(hz);
    float rw = a.w - __bfloat162float(hw);
    hi[2 * i]     = __halves2bfloat162(hx, hy);
    hi[2 * i + 1] = __halves2bfloat162(hz, hw);
    lo[2 * i]     = __halves2bfloat162(__float2bfloat16(rx), __float2bfloat16(ry));
    lo[2 * i + 1] = __halves2bfloat162(__float2bfloat16(rz), __float2bfloat16(rw));
}

// ---------------------------------------------------------------------------
// fp32 -> fp16 hi/lo split (activations, main path)
// ---------------------------------------------------------------------------
__global__ void splitH_kernel(const float4* __restrict__ in,
                              __half2* __restrict__ hi,
                              __half2* __restrict__ lo, int n4)
{
    int i = blockIdx.x * blockDim.x + threadIdx.x;
    if (i >= n4) return;
    float4 a = in[i];
    __half hx = __float2half_rn(a.x);
    __half hy = __float2half_rn(a.y);
    __half hz = __float2half_rn(a.z);
    __half hw = __float2half_rn(a.w);
    float rx = a.x - __half2float(hx);
    float ry = a.y - __half2float(hy);
    float rz = a.z - __half2float(hz);
    float rw = a.w - __half2float(hw);
    hi[2 * i]     = __halves2half2(hx, hy);
    hi[2 * i + 1] = __halves2half2(hz, hw);
    lo[2 * i]     = __halves2half2(__float2half_rn(rx), __float2half_rn(ry));
    lo[2 * i + 1] = __halves2half2(__float2half_rn(rz), __float2half_rn(rw));
}

// fp32 -> fp16 single (weights)
__global__ void cvtH_kernel(const float4* __restrict__ in,
                            __half2* __restrict__ out, int n4)
{
    int i = blockIdx.x * blockDim.x + threadIdx.x;
    if (i >= n4) return;
    float4 a = in[i];
    out[2 * i]     = __halves2half2(__float2half_rn(a.x), __float2half_rn(a.y));
    out[2 * i + 1] = __halves2half2(__float2half_rn(a.z), __float2half_rn(a.w));
}

// ---------------------------------------------------------------------------
// fp16 2-pass batched tensor GEMM: C[z] = (Ah + Al) @ B[z]
// A split in fp16 hi/lo [M,K] row-major; B single fp16 [K,N] row-major.
// 128x128 CTA tile, BK=32, 256 threads (8 warps, warp tile 64x32),
// cp.async double-buffered, 2 CTAs/SM.
// ---------------------------------------------------------------------------
#define BKC 32
#define A_STR 40                        // 16-bit units (80 bytes)
#define B_STR 136                       // 16-bit units (272 bytes)
#define HSLOT_A (128 * A_STR * 2)       // 10240
#define HSLOT_B (BKC * B_STR * 2)       // 8704
#define HBUF (2 * HSLOT_A + HSLOT_B)    // 29184
#define HOFF_AH(buf) ((buf) * HBUF)
#define HOFF_B(buf)  ((buf) * HBUF + 2 * HSLOT_A)
#define HGEMM_SMEM (2 * HBUF)           // 58368

struct HGemmTriple {
    const __half* B;
    float* C;
};
struct HGemmBatch {
    const __half* Ah;
    const __half* Al;
    HGemmTriple t[4];
};

__device__ __forceinline__ void hgemm_load(
    uint32_t sb, int buf,
    const __half* __restrict__ Ah, const __half* __restrict__ Al,
    const __half* __restrict__ B,
    int m0, int n0, int k0, int K, int N, int tid)
{
#pragma unroll
    for (int r = 0; r < 2; r++) {
        int i = tid + (r << 8);
        int row = i >> 2;
        int kc  = (i & 3) << 3;          // 16-bit units
        uint32_t da = sb + HOFF_AH(buf) + row * (A_STR * 2) + kc * 2;
        CP16(da,           (const void*)(Ah + (size_t)(m0 + row) * K + k0 + kc));
        CP16(da + HSLOT_A, (const void*)(Al + (size_t)(m0 + row) * K + k0 + kc));
    }
#pragma unroll
    for (int r = 0; r < 2; r++) {
        int i = tid + (r << 8);
        int krow = i >> 4;
        int nc   = (i & 15) << 3;
        uint32_t db = sb + HOFF_B(buf) + krow * (B_STR * 2) + nc * 2;
        CP16(db, (const void*)(B + (size_t)(k0 + krow) * N + n0 + nc));
    }
}

__global__ void __launch_bounds__(256, 2)
hgemm_kernel(HGemmBatch gbat, int M, int N, int K)
{
    extern __shared__ char smem[];
    const uint32_t sb = smem_u32(smem);
    const int tid  = threadIdx.x;
    const int lane = tid & 31;
    const int wid  = tid >> 5;
    const int wm0  = (wid >> 2) * 64;
    const int wn0  = (wid & 3) * 32;
    const int m0 = blockIdx.y * 128;
    const int n0 = blockIdx.x * 128;

    const __half* __restrict__ Ah = gbat.Ah;
    const __half* __restrict__ Al = gbat.Al;
    const __half* __restrict__ B  = gbat.t[blockIdx.z].B;
    float* __restrict__ C = gbat.t[blockIdx.z].C;

    float acc[4][4][4];
#pragma unroll
    for (int a = 0; a < 4; a++)
#pragma unroll
        for (int b = 0; b < 4; b++)
#pragma unroll
            for (int c = 0; c < 4; c++) acc[a][b][c] = 0.f;

    const int nch = K / BKC;
    hgemm_load(sb, 0, Ah, Al, B, m0, n0, 0, K, N, tid);
    CP_COMMIT();

    for (int ch = 0; ch < nch; ch++) {
        const int buf = ch & 1;
        if (ch + 1 < nch) {
            hgemm_load(sb, buf ^ 1, Ah, Al, B, m0, n0, (ch + 1) * BKC, K, N, tid);
            CP_COMMIT();
            CP_WAIT1();
        } else {
            CP_WAIT0();
        }
        __syncthreads();

        const uint32_t aBase = sb + HOFF_AH(buf);
        const uint32_t bBase = sb + HOFF_B(buf);

#pragma unroll
        for (int kk = 0; kk < 2; kk++) {
            const int kb = kk * 16;
            uint32_t Af[4][4], Bf[2][4];

            const int arow = wm0 + (lane & 15);
            const uint32_t kcol = (uint32_t)(kb + ((lane >> 4) << 3)) * 2;
            const int krow = kb + (lane & 15);

            // B fragments (single tensor)
#pragma unroll
            for (int nb2 = 0; nb2 < 2; nb2++) {
                uint32_t nby = (uint32_t)(wn0 + nb2 * 16 + ((lane >> 4) << 3)) * 2;
                LDSM4T(Bf[nb2], bBase + (uint32_t)krow * (B_STR * 2) + nby);
            }
            // A-hi fragments
#pragma unroll
            for (int mb = 0; mb < 4; mb++) {
                uint32_t ad = aBase + (uint32_t)(arow + mb * 16) * (A_STR * 2) + kcol;
                LDSM4(Af[mb], ad);
            }
            // pass 1: Ah * B
#pragma unroll
            for (int mb = 0; mb < 4; mb++) {
#pragma unroll
                for (int nb = 0; nb < 4; nb++) {
                    uint32_t b0 = Bf[nb >> 1][(nb & 1) << 1];
                    uint32_t b1 = Bf[nb >> 1][((nb & 1) << 1) | 1];
                    MMA_F16(acc[mb][nb], Af[mb], b0, b1);
                }
            }
            // A-lo fragments (reuse regs)
#pragma unroll
            for (int mb = 0; mb < 4; mb++) {
                uint32_t ad = aBase + HSLOT_A
                            + (uint32_t)(arow + mb * 16) * (A_STR * 2) + kcol;
                LDSM4(Af[mb], ad);
            }
            // pass 2: Al * B
#pragma unroll
            for (int mb = 0; mb < 4; mb++) {
#pragma unroll
                for (int nb = 0; nb < 4; nb++) {
                    uint32_t b0 = Bf[nb >> 1][(nb & 1) << 1];
                    uint32_t b1 = Bf[nb >> 1][((nb & 1) << 1) | 1];
                    MMA_F16(acc[mb][nb], Af[mb], b0, b1);
                }
            }
        }
        __syncthreads();
    }

#pragma unroll
    for (int mb = 0; mb < 4; mb++) {
#pragma unroll
        for (int nb = 0; nb < 4; nb++) {
            int r = m0 + wm0 + mb * 16 + (lane >> 2);
            int c = n0 + wn0 + nb * 8 + ((lane & 3) << 1);
            float2 v0 = make_float2(acc[mb][nb][0], acc[mb][nb][1]);
            float2 v1 = make_float2(acc[mb][nb][2], acc[mb][nb][3]);
            *(float2*)&C[(size_t)r * N + c]       = v0;
            *(float2*)&C[(size_t)(r + 8) * N + c] = v1;
        }
    }
}

// ---------------------------------------------------------------------------
// bf16-split 3-pass tensor GEMM (gate path: f1, f2) — unchanged from R9
// ---------------------------------------------------------------------------
#define SA_SLOT (128 * A_STR * 2)
#define SB_SLOT (BKC * B_STR * 2)
#define ABYTES (4 * SA_SLOT)
#define OFF_A(buf, hl) ((buf) * 2 * SA_SLOT + (hl) * SA_SLOT)
#define OFF_B(buf, hl) (ABYTES + (buf) * 2 * SB_SLOT + (hl) * SB_SLOT)
#define GEMM_SMEM (ABYTES + 4 * SB_SLOT)

__device__ __forceinline__ void gemm_load_chunk(
    uint32_t sb, int buf,
    const __nv_bfloat16* __restrict__ Ah, const __nv_bfloat16* __restrict__ Al,
    const __nv_bfloat16* __restrict__ Bh, const __nv_bfloat16* __restrict__ Bl,
    int m0, int n0, int k0, int K, int N, int tid)
{
#pragma unroll
    for (int r = 0; r < 2; r++) {
        int i = tid + (r << 8);
        int row = i >> 2;
        int kc  = (i & 3) << 3;
        uint32_t da = sb + OFF_A(buf, 0) + row * (A_STR * 2) + kc * 2;
        CP16(da, (const void*)(Ah + (size_t)(m0 + row) * K + k0 + kc));
        CP16(da + SA_SLOT, (const void*)(Al + (size_t)(m0 + row) * K + k0 + kc));
    }
#pragma unroll
    for (int r = 0; r < 2; r++) {
        int i = tid + (r << 8);
        int krow = i >> 4;
        int nc   = (i & 15) << 3;
        uint32_t db = sb + OFF_B(buf, 0) + krow * (B_STR * 2) + nc * 2;
        CP16(db, (const void*)(Bh + (size_t)(k0 + krow) * N + n0 + nc));
        CP16(db + SB_SLOT, (const void*)(Bl + (size_t)(k0 + krow) * N + n0 + nc));
    }
}

__global__ void __launch_bounds__(256, 2)
tgemm_kernel(const __nv_bfloat16* __restrict__ Ah,
             const __nv_bfloat16* __restrict__ Al,
             const __nv_bfloat16* __restrict__ Bh,
             const __nv_bfloat16* __restrict__ Bl,
             float* __restrict__ C, int M, int N, int K)
{
    extern __shared__ char smem[];
    const uint32_t sb = smem_u32(smem);
    const int tid  = threadIdx.x;
    const int lane = tid & 31;
    const int wid  = tid >> 5;
    const int wm0  = (wid >> 2) * 64;
    const int wn0  = (wid & 3) * 32;
    const int m0 = blockIdx.y * 128;
    const int n0 = blockIdx.x * 128;

    float acc[4][4][4];
#pragma unroll
    for (int a = 0; a < 4; a++)
#pragma unroll
        for (int b = 0; b < 4; b++)
#pragma unroll
            for (int c = 0; c < 4; c++) acc[a][b][c] = 0.f;

    const int nch = K / BKC;
    gemm_load_chunk(sb, 0, Ah, Al, Bh, Bl, m0, n0, 0, K, N, tid);
    CP_COMMIT();

    for (int ch = 0; ch < nch; ch++) {
        const int buf = ch & 1;
        if (ch + 1 < nch) {
            gemm_load_chunk(sb, buf ^ 1, Ah, Al, Bh, Bl,
                            m0, n0, (ch + 1) * BKC, K, N, tid);
            CP_COMMIT();
            CP_WAIT1();
        } else {
            CP_WAIT0();
        }
        __syncthreads();

        const uint32_t aBase = sb + OFF_A(buf, 0);
        const uint32_t bBase = sb + OFF_B(buf, 0);

#pragma unroll
        for (int kk = 0; kk < 2; kk++) {
            const int kb = kk * 16;
            uint32_t Af[4][4], Bhf[2][4], Blf[2][4];
            const int arow = wm0 + (lane & 15);
            const uint32_t kcol = (uint32_t)(kb + ((lane >> 4) << 3)) * 2;
            const int krow = kb + (lane & 15);

#pragma unroll
            for (int nb2 = 0; nb2 < 2; nb2++) {
                uint32_t nby = (uint32_t)(wn0 + nb2 * 16 + ((lane >> 4) << 3)) * 2;
                uint32_t bd = bBase + (uint32_t)krow * (B_STR * 2) + nby;
                LDSM4T(Bhf[nb2], bd);
                LDSM4T(Blf[nb2], bd + SB_SLOT);
            }
#pragma unroll
            for (int mb = 0; mb < 4; mb++) {
                uint32_t ad = aBase + (uint32_t)(arow + mb * 16) * (A_STR * 2) + kcol;
                LDSM4(Af[mb], ad);
            }
#pragma unroll
            for (int mb = 0; mb < 4; mb++) {
#pragma unroll
                for (int nb = 0; nb < 4; nb++) {
                    uint32_t bh0 = Bhf[nb >> 1][(nb & 1) << 1];
                    uint32_t bh1 = Bhf[nb >> 1][((nb & 1) << 1) | 1];
                    uint32_t bl0 = Blf[nb >> 1][(nb & 1) << 1];
                    uint32_t bl1 = Blf[nb >> 1][((nb & 1) << 1) | 1];
                    MMA_BF16(acc[mb][nb], Af[mb], bh0, bh1);
                    MMA_BF16(acc[mb][nb], Af[mb], bl0, bl1);
                }
            }
#pragma unroll
            for (int mb = 0; mb < 4; mb++) {
                uint32_t ad = aBase + SA_SLOT
                            + (uint32_t)(arow + mb * 16) * (A_STR * 2) + kcol;
                LDSM4(Af[mb], ad);
            }
#pragma unroll
            for (int mb = 0; mb < 4; mb++) {
#pragma unroll
                for (int nb = 0; nb < 4; nb++) {
                    uint32_t bh0 = Bhf[nb >> 1][(nb & 1) << 1];
                    uint32_t bh1 = Bhf[nb >> 1][((nb & 1) << 1) | 1];
                    MMA_BF16(acc[mb][nb], Af[mb], bh0, bh1);
                }
            }
        }
        __syncthreads();
    }

#pragma unroll
    for (int mb = 0; mb < 4; mb++) {
#pragma unroll
        for (int nb = 0; nb < 4; nb++) {
            int r = m0 + wm0 + mb * 16 + (lane >> 2);
            int c = n0 + wn0 + nb * 8 + ((lane & 3) << 1);
            float2 v0 = make_float2(acc[mb][nb][0], acc[mb][nb][1]);
            float2 v1 = make_float2(acc[mb][nb][2], acc[mb][nb][3]);
            *(float2*)&C[(size_t)r * N + c]       = v0;
            *(float2*)&C[(size_t)(r + 8) * N + c] = v1;
        }
    }
}

// ---------------------------------------------------------------------------
// beta = sigmoid(x @ Wb)
// ---------------------------------------------------------------------------
__global__ __launch_bounds__(128) void beta_kernel(
    const float* __restrict__ x, const float* __restrict__ Wb,
    float* __restrict__ beta)
{
    const int m = blockIdx.x;
    const int tid = threadIdx.x;
    const float* xr = x + (size_t)m * DIM;

    float acc[NH];
#pragma unroll
    for (int h = 0; h < NH; h++) acc[h] = 0.f;

    for (int k = tid; k < DIM; k += 128) {
        float xv = xr[k];
        const float* wr = Wb + (size_t)k * NH;
#pragma unroll
        for (int h = 0; h < NH; h++) acc[h] += xv * wr[h];
    }

    __shared__ float sh[128 * NH];
#pragma unroll
    for (int h = 0; h < NH; h++) sh[tid * NH + h] = acc[h];
    __syncthreads();

    if (tid < NH) {
        float s = 0.f;
        for (int i = 0; i < 128; i++) s += sh[i * NH + tid];
        beta[(size_t)m * NH + tid] = 1.f / (1.f + expf(-s));
    }
}

// ---------------------------------------------------------------------------
// Causal depthwise conv (K=4) + SiLU (+ per-head L2 norm)
// ---------------------------------------------------------------------------
template <bool NORM>
__global__ __launch_bounds__(128) void conv_kernel(
    const float* __restrict__ xin, const float* __restrict__ w,
    float* __restrict__ out)
{
    const int TT = 32;
    const int t0 = blockIdx.x * TT;
    const int c0 = blockIdx.y * 128;
    const int b  = blockIdx.z;
    const int tid = threadIdx.x;
    const int c = c0 + tid;

    __shared__ float xsh[TT + 3][128];
    __shared__ float ysh[TT][128];
    __shared__ float rns[TT];

    const float* xb = xin + ((size_t)b * SEQ) * DIM + c;
#pragma unroll
    for (int r = 0; r < TT + 3; r++) {
        int t = t0 - 3 + r;
        xsh[r][tid] = (t >= 0) ? xb[(size_t)t * DIM] : 0.f;
    }
    float4 wv = *(const float4*)(w + (size_t)c * 4);
    __syncthreads();

    float yreg[TT];
#pragma unroll
    for (int tt = 0; tt < TT; tt++) {
        float y = xsh[tt][tid] * wv.x + xsh[tt + 1][tid] * wv.y
                + xsh[tt + 2][tid] * wv.z + xsh[tt + 3][tid] * wv.w;
        y = y / (1.f + expf(-y));
        yreg[tt] = y;
        if (NORM) ysh[tt][tid] = y;
    }

    if (NORM) {
        __syncthreads();
        const int wd = tid >> 5, lane = tid & 31;
        for (int tt = wd; tt < TT; tt += 4) {
            float a0 = ysh[tt][lane],      a1 = ysh[tt][lane + 32];
            float a2 = ysh[tt][lane + 64], a3 = ysh[tt][lane + 96];
            float s = a0 * a0 + a1 * a1 + a2 * a2 + a3 * a3;
#pragma unroll
            for (int off = 16; off > 0; off >>= 1)
                s += __shfl_xor_sync(0xFFFFFFFFu, s, off);
            if (lane == 0) rns[tt] = rsqrtf(s + 1e-6f);
        }
        __syncthreads();
    }

    float* ob = out + ((size_t)b * SEQ) * DIM + c;
#pragma unroll
    for (int tt = 0; tt < TT; tt++) {
        float y = yreg[tt];
        if (NORM) y *= rns[tt];
        ob[(size_t)(t0 + tt) * DIM] = y;
    }
}

// ---------------------------------------------------------------------------
// gexp
// ---------------------------------------------------------------------------
__global__ void gexp_kernel(float* __restrict__ g,
                            const float* __restrict__ A_log,
                            const float* __restrict__ dt_bias, int n)
{
    int i = blockIdx.x * blockDim.x + threadIdx.x;
    if (i >= n) return;
    int c = i & (DIM - 1);
    int h = c >> 7;
    float a = -expf(A_log[h]);
    float u = g[i] + dt_bias[c];
    float sp = (u > 20.f) ? u : log1pf(expf(u));
    g[i] = expf(a * sp);
}

// ---------------------------------------------------------------------------
// Delta-rule scan, barrier-free (as R9).
// ---------------------------------------------------------------------------
#define SCAN_LOAD(J, qb_, kb_, gb_, vt_, bt_, tt)                              \
    do {                                                                       \
        const float4* _qp = qp + (size_t)(tt) * ST4;                           \
        const float4* _kp = kp + (size_t)(tt) * ST4;                           \
        const float4* _gp = gp + (size_t)(tt) * ST4;                           \
        _Pragma("unroll")                                                      \
        for (int j = 0; j < 4; j++) {                                          \
            qb_[j] = _qp[j]; kb_[j] = _kp[j]; gb_[j] = _gp[j];                 \
        }                                                                      \
        vt_ = v[vbase + (size_t)(tt) * (NH * DV)];                             \
        bt_ = beta[bbase + (size_t)(tt) * NH];                                 \
    } while (0)

#define SCAN_STEP(qb_, kb_, gb_, vt_, bt_, tt)                                 \
    do {                                                                       \
        float kv0 = 0.f, kv1 = 0.f, kv2 = 0.f, kv3 = 0.f;                      \
        _Pragma("unroll")                                                      \
        for (int ii = 0; ii < 4; ii++) {                                       \
            float4 kk4 = kb_[ii]; float4 gg4 = gb_[ii];                        \
            S[4*ii+0] *= gg4.x; kv0 += kk4.x * S[4*ii+0];                      \
            S[4*ii+1] *= gg4.y; kv1 += kk4.y * S[4*ii+1];                      \
            S[4*ii+2] *= gg4.z; kv2 += kk4.z * S[4*ii+2];                      \
            S[4*ii+3] *= gg4.w; kv3 += kk4.w * S[4*ii+3];                      \
        }                                                                      \
        float kv = (kv0 + kv1) + (kv2 + kv3);                                  \
        kv += __shfl_xor_sync(0xFFFFFFFFu, kv, 1);                             \
        kv += __shfl_xor_sync(0xFFFFFFFFu, kv, 2);                             \
        kv += __shfl_xor_sync(0xFFFFFFFFu, kv, 4);                             \
        float upd = (vt_ - kv) * bt_;                                          \
        float ov0 = 0.f, ov1 = 0.f, ov2 = 0.f, ov3 = 0.f;                      \
        _Pragma("unroll")                                                      \
        for (int ii = 0; ii < 4; ii++) {                                       \
            float4 kk4 = kb_[ii]; float4 qq4 = qb_[ii];                        \
            S[4*ii+0] += kk4.x * upd; ov0 += qq4.x * S[4*ii+0];                \
            S[4*ii+1] += kk4.y * upd; ov1 += qq4.y * S[4*ii+1];                \
            S[4*ii+2] += kk4.z * upd; ov2 += qq4.z * S[4*ii+2];                \
            S[4*ii+3] += kk4.w * upd; ov3 += qq4.w * S[4*ii+3];                \
        }                                                                      \
        float ov = (ov0 + ov1) + (ov2 + ov3);                                  \
        ov += __shfl_xor_sync(0xFFFFFFFFu, ov, 1);                             \
        ov += __shfl_xor_sync(0xFFFFFFFFu, ov, 2);                             \
        ov += __shfl_xor_sync(0xFFFFFFFFu, ov, 4);                             \
        if (s == 0) o[vbase + (size_t)(tt) * (NH * DV)] = ov * scale;          \
    } while (0)

__global__ __launch_bounds__(256) void scan_kernel(
    const float* __restrict__ q, const float* __restrict__ k,
    const float* __restrict__ v, const float* __restrict__ ge,
    const float* __restrict__ beta, float* __restrict__ o)
{
    const int bh = blockIdx.x >> 2;
    const int cg = blockIdx.x & 3;
    const int b  = bh / NH, h = bh % NH;
    const int tid = threadIdx.x;
    const int s   = tid & 7;
    const int col = cg * 32 + (tid >> 3);

    const float scale = 0.08838834764831845f;
    const size_t kbase = ((size_t)(b * SEQ) * NH + h) * (size_t)DK + s * 16;
    const size_t vbase = ((size_t)(b * SEQ) * NH + h) * (size_t)DV + col;
    const size_t bbase = (size_t)(b * SEQ) * NH + h;
    const int ST4 = (NH * DK) / 4;

    const float4* qp = (const float4*)(q + kbase);
    const float4* kp = (const float4*)(k + kbase);
    const float4* gp = (const float4*)(ge + kbase);

    float S[16];
#pragma unroll
    for (int i = 0; i < 16; i++) S[i] = 0.f;

    float4 q0[4], k0[4], g0[4], q1[4], k1[4], g1[4];
    float vt0, bt0, vt1, bt1;

    SCAN_LOAD(0, q0, k0, g0, vt0, bt0, 0);

    for (int t = 0; t < SEQ; t += 2) {
        SCAN_LOAD(1, q1, k1, g1, vt1, bt1, t + 1);
        SCAN_STEP(q0, k0, g0, vt0, bt0, t);
        if (t + 2 < SEQ)
            SCAN_LOAD(0, q0, k0, g0, vt0, bt0, t + 2);
        SCAN_STEP(q1, k1, g1, vt1, bt1, t + 1);
    }
}

// ---------------------------------------------------------------------------
// Epilogue: gated RMSNorm, fused with fp16 hi/lo split of the result
// ---------------------------------------------------------------------------
__global__ __launch_bounds__(128) void epilogue_kernel(
    const float* __restrict__ o, const float* __restrict__ gate,
    const float* __restrict__ bg, const float* __restrict__ onw,
    __half* __restrict__ oh, __half* __restrict__ ol)
{
    const int m = blockIdx.x;
    const int h = blockIdx.y;
    const int tid = threadIdx.x;
    size_t idx = ((size_t)m * NH + h) * (size_t)DV + tid;

    float ov = o[idx];
    float s = ov * ov;
#pragma unroll
    for (int off = 16; off > 0; off >>= 1)
        s += __shfl_xor_sync(0xFFFFFFFFu, s, off);

    __shared__ float ws[4];
    const int wd = tid >> 5, lane = tid & 31;
    if (lane == 0) ws[wd] = s;
    __syncthreads();
    float tot = ws[0] + ws[1] + ws[2] + ws[3];

    float r = rsqrtf(tot * (1.f / 128.f) + 1e-5f);
    float gv = gate[idx] + bg[h * DV + tid];
    float sig = 1.f / (1.f + expf(-gv));
    float f = ov * r * onw[tid] * (gv * sig);

    __half fh = __float2half_rn(f);
    oh[idx] = fh;
    ol[idx] = __float2half_rn(f - __half2float(fh));
}

// ---------------------------------------------------------------------------
// kernel_launch
// ---------------------------------------------------------------------------
static inline void do_split(const float* src, __nv_bfloat16* hi,
                            __nv_bfloat16* lo, int n)
{
    int n4 = n >> 2;
    split_kernel<<<(n4 + 255) / 256, 256>>>(
        (const float4*)src, (__nv_bfloat162*)hi, (__nv_bfloat162*)lo, n4);
}

static inline void do_splitH(const float* src, __half* hi, __half* lo, int n)
{
    int n4 = n >> 2;
    splitH_kernel<<<(n4 + 255) / 256, 256>>>(
        (const float4*)src, (__half2*)hi, (__half2*)lo, n4);
}

static inline void do_cvtH(const float* src, __half* dst, int n)
{
    int n4 = n >> 2;
    cvtH_kernel<<<(n4 + 255) / 256, 256>>>(
        (const float4*)src, (__half2*)dst, n4);
}

extern "C" void kernel_launch(void* const* d_in, const int* in_sizes, int n_in,
                              void* d_out, int out_size)
{
    const float* x       = (const float*)d_in[0];
    const float* Wq      = (const float*)d_in[1];
    const float* Wk      = (const float*)d_in[2];
    const float* Wv      = (const float*)d_in[3];
    const float* conv_q  = (const float*)d_in[4];
    const float* conv_k  = (const float*)d_in[5];
    const float* conv_v  = (const float*)d_in[6];
    const float* Wf1     = (const float*)d_in[7];
    const float* Wf2     = (const float*)d_in[8];
    const float* Wb      = (const float*)d_in[9];
    const float* A_log   = (const float*)d_in[10];
    const float* dt_bias = (const float*)d_in[11];
    const float* Wg      = (const float*)d_in[12];
    const float* bg      = (const float*)d_in[13];
    const float* o_norm_w= (const float*)d_in[14];
    const float* Wo      = (const float*)d_in[15];
    float* out = (float*)d_out;

    cudaFuncSetAttribute(tgemm_kernel,
                         cudaFuncAttributeMaxDynamicSharedMemorySize, GEMM_SMEM);
    cudaFuncSetAttribute(hgemm_kernel,
                         cudaFuncAttributeMaxDynamicSharedMemorySize, HGEMM_SMEM);

    float *qpre, *kpre, *vpre, *qb, *kb, *vb, *gateb, *gb, *ob, *f1b, *betab;
    cudaGetSymbolAddress((void**)&qpre,  g_qpre);
    cudaGetSymbolAddress((void**)&kpre,  g_kpre);
    cudaGetSymbolAddress((void**)&vpre,  g_vpre);
    cudaGetSymbolAddress((void**)&qb,    g_q);
    cudaGetSymbolAddress((void**)&kb,    g_k);
    cudaGetSymbolAddress((void**)&vb,    g_v);
    cudaGetSymbolAddress((void**)&gateb, g_gate);
    cudaGetSymbolAddress((void**)&gb,    g_g);
    cudaGetSymbolAddress((void**)&ob,    g_o);
    cudaGetSymbolAddress((void**)&f1b,   g_f1);
    cudaGetSymbolAddress((void**)&betab, g_beta);

    __nv_bfloat16 *xbh, *xbl, *wf1h, *wf1l, *wf2h, *wf2l, *f1h, *f1l;
    cudaGetSymbolAddress((void**)&xbh,  g_xbh);  cudaGetSymbolAddress((void**)&xbl,  g_xbl);
    cudaGetSymbolAddress((void**)&wf1h, g_wf1h); cudaGetSymbolAddress((void**)&wf1l, g_wf1l);
    cudaGetSymbolAddress((void**)&wf2h, g_wf2h); cudaGetSymbolAddress((void**)&wf2l, g_wf2l);
    cudaGetSymbolAddress((void**)&f1h,  g_f1h);  cudaGetSymbolAddress((void**)&f1l,  g_f1l);

    __half *xhh, *xhl, *ohh, *ohl, *hwq, *hwk, *hwv, *hwg, *hwo;
    cudaGetSymbolAddress((void**)&xhh, g_xhh); cudaGetSymbolAddress((void**)&xhl, g_xhl);
    cudaGetSymbolAddress((void**)&ohh, g_ohh); cudaGetSymbolAddress((void**)&ohl, g_ohl);
    cudaGetSymbolAddress((void**)&hwq, g_hwq); cudaGetSymbolAddress((void**)&hwk, g_hwk);
    cudaGetSymbolAddress((void**)&hwv, g_hwv); cudaGetSymbolAddress((void**)&hwg, g_hwg);
    cudaGetSymbolAddress((void**)&hwo, g_hwo);

    // --- fp16 prep for main path ---
    do_splitH(x, xhh, xhl, NELEM);
    do_cvtH(Wq, hwq, WSZ);
    do_cvtH(Wk, hwk, WSZ);
    do_cvtH(Wv, hwv, WSZ);
    do_cvtH(Wg, hwg, WSZ);
    do_cvtH(Wo, hwo, WSZ);

    // --- batched QKVG projection (fp16 2-pass tensor cores) ---
    {
        HGemmBatch gbat;
        gbat.Ah = xhh; gbat.Al = xhl;
        gbat.t[0] = { hwq, qpre };
        gbat.t[1] = { hwk, kpre };
        gbat.t[2] = { hwv, vpre };
        gbat.t[3] = { hwg, gateb };
        dim3 g(DIM / 128, MTOT / 128, 4);
        hgemm_kernel<<<g, 256, HGEMM_SMEM>>>(gbat, MTOT, DIM, DIM);
    }

    // --- gate path (bf16 3-pass, precision-critical) ---
    do_split(x,   xbh,  xbl,  NELEM);
    do_split(Wf1, wf1h, wf1l, DIM * DV);
    do_split(Wf2, wf2h, wf2l, DV * DIM);
    {
        dim3 g(DV / 128, MTOT / 128, 1);
        tgemm_kernel<<<g, 256, GEMM_SMEM>>>(xbh, xbl, wf1h, wf1l, f1b, MTOT, DV, DIM);
    }
    do_split(f1b, f1h, f1l, MTOT * DV);
    {
        dim3 g(DIM / 128, MTOT / 128, 1);
        tgemm_kernel<<<g, 256, GEMM_SMEM>>>(f1h, f1l, wf2h, wf2l, gb, MTOT, DIM, DV);
    }

    beta_kernel<<<MTOT, 128>>>(x, Wb, betab);

    // --- conv + silu (+ l2norm for q,k) ---
    dim3 gConv(SEQ / 32, DIM / 128, BATCH);
    conv_kernel<true ><<<gConv, 128>>>(qpre, conv_q, qb);
    conv_kernel<true ><<<gConv, 128>>>(kpre, conv_k, kb);
    conv_kernel<false><<<gConv, 128>>>(vpre, conv_v, vb);

    // --- decay gates ---
    gexp_kernel<<<NELEM / 256, 256>>>(gb, A_log, dt_bias, NELEM);

    // --- delta-rule scan (barrier-free) ---
    scan_kernel<<<BATCH * NH * 4, 256>>>(qb, kb, vb, gb, betab, ob);

    // --- gated RMSNorm epilogue fused with fp16 hi/lo split ---
    dim3 gEpi(MTOT, NH);
    epilogue_kernel<<<gEpi, 128>>>(ob, gateb, bg, o_norm_w, ohh, ohl);

    // --- output projection (fp16 2-pass) ---
    {
        HGemmBatch gbat;
        gbat.Ah = ohh; gbat.Al = ohl;
        gbat.t[0] = { hwo, out };
        gbat.t[1] = gbat.t[0]; gbat.t[2] = gbat.t[0]; gbat.t[3] = gbat.t[0];
        dim3 g(DIM / 128, MTOT / 128, 1);
        hgemm_kernel<<<g, 256, HGEMM_SMEM>>>(gbat, MTOT, DIM, DIM);
    }
}

// round 12
// speedup vs baseline: 2.2598x; 1.0600x over previous
#include <cuda_runtime.h>
#include <cuda_bf16.h>
#include <cuda_fp16.h>
#include <math.h>
#include <stdint.h>

// ---------------------------------------------------------------------------
// Problem constants
// ---------------------------------------------------------------------------
#define BATCH 2
#define SEQ   2048
#define DIM   2048
#define NH    16
#define DK    128
#define DV    128
#define MTOT  (BATCH * SEQ)          // 4096
#define NELEM (MTOT * DIM)           // 8388608
#define WSZ   (DIM * DIM)            // 4194304

// ---------------------------------------------------------------------------
// Device scratch
// ---------------------------------------------------------------------------
__device__ float g_qpre[NELEM];
__device__ float g_kpre[NELEM];
__device__ float g_vpre[NELEM];
__device__ float g_q[NELEM];
__device__ float g_k[NELEM];
__device__ float g_v[NELEM];
__device__ float g_gate[NELEM];
__device__ float g_g[NELEM];
__device__ float g_o[NELEM];
__device__ float g_f1[MTOT * DV];
__device__ float g_beta[MTOT * NH];

// bf16 split buffers (gate path)
__device__ __nv_bfloat16 g_xbh[NELEM],  g_xbl[NELEM];
__device__ __nv_bfloat16 g_wf1h[DIM*DV], g_wf1l[DIM*DV];
__device__ __nv_bfloat16 g_wf2h[DV*DIM], g_wf2l[DV*DIM];
__device__ __nv_bfloat16 g_f1h[MTOT*DV], g_f1l[MTOT*DV];

// fp16 buffers (main GEMM path)
__device__ __half g_xhh[NELEM], g_xhl[NELEM];
__device__ __half g_ohh[NELEM], g_ohl[NELEM];
__device__ __half g_hwq[WSZ], g_hwk[WSZ], g_hwv[WSZ], g_hwg[WSZ], g_hwo[WSZ];

// ---------------------------------------------------------------------------
// PTX helpers (baseline ISA: mma.sync / ldmatrix / cp.async)
// ---------------------------------------------------------------------------
__device__ __forceinline__ uint32_t smem_u32(const void* p) {
    uint32_t a;
    asm("{ .reg .u64 t; cvta.to.shared.u64 t, %1; cvt.u32.u64 %0, t; }"
        : "=r"(a) : "l"(p));
    return a;
}

#define CP16(dst, src) \
    asm volatile("cp.async.cg.shared.global [%0], [%1], 16;" \
                 :: "r"(dst), "l"(src))
#define CP_COMMIT() asm volatile("cp.async.commit_group;" ::: "memory")
#define CP_WAIT0()  asm volatile("cp.async.wait_group 0;" ::: "memory")
#define CP_WAIT1()  asm volatile("cp.async.wait_group 1;" ::: "memory")

#define LDSM4(R, addr)                                                         \
    asm volatile("ldmatrix.sync.aligned.m8n8.x4.shared.b16 {%0,%1,%2,%3}, [%4];" \
        : "=r"((R)[0]), "=r"((R)[1]), "=r"((R)[2]), "=r"((R)[3]) : "r"(addr))

#define LDSM4T(R, addr)                                                        \
    asm volatile("ldmatrix.sync.aligned.m8n8.x4.trans.shared.b16 {%0,%1,%2,%3}, [%4];" \
        : "=r"((R)[0]), "=r"((R)[1]), "=r"((R)[2]), "=r"((R)[3]) : "r"(addr))

#define MMA_BF16(C4, A4, b0, b1)                                               \
    asm volatile("mma.sync.aligned.m16n8k16.row.col.f32.bf16.bf16.f32 "        \
        "{%0,%1,%2,%3},{%4,%5,%6,%7},{%8,%9},{%0,%1,%2,%3};"                   \
        : "+f"((C4)[0]), "+f"((C4)[1]), "+f"((C4)[2]), "+f"((C4)[3])           \
        : "r"((A4)[0]), "r"((A4)[1]), "r"((A4)[2]), "r"((A4)[3]),              \
          "r"(b0), "r"(b1))

#define MMA_F16(C4, A4, b0, b1)                                                \
    asm volatile("mma.sync.aligned.m16n8k16.row.col.f32.f16.f16.f32 "          \
        "{%0,%1,%2,%3},{%4,%5,%6,%7},{%8,%9},{%0,%1,%2,%3};"                   \
        : "+f"((C4)[0]), "+f"((C4)[1]), "+f"((C4)[2]), "+f"((C4)[3])           \
        : "r"((A4)[0]), "r"((A4)[1]), "r"((A4)[2]), "r"((A4)[3]),              \
          "r"(b0), "r"(b1))

// ---------------------------------------------------------------------------
// Fused split of x: fp32 -> fp16 hi/lo AND bf16 hi/lo in one read pass
// ---------------------------------------------------------------------------
__global__ void splitHB_kernel(const float4* __restrict__ in,
                               __half2* __restrict__ hh, __half2* __restrict__ hl,
                               __nv_bfloat162* __restrict__ bh,
                               __nv_bfloat162* __restrict__ bl, int n4)
{
    int i = blockIdx.x * blockDim.x + threadIdx.x;
    if (i >= n4) return;
    float4 a = in[i];
    // fp16 split
    __half px = __float2half_rn(a.x), py = __float2half_rn(a.y);
    __half pz = __float2half_rn(a.z), pw = __float2half_rn(a.w);
    hh[2 * i]     = __halves2half2(px, py);
    hh[2 * i + 1] = __halves2half2(pz, pw);
    hl[2 * i]     = __halves2half2(__float2half_rn(a.x - __half2float(px)),
                                   __float2half_rn(a.y - __half2float(py)));
    hl[2 * i + 1] = __halves2half2(__float2half_rn(a.z - __half2float(pz)),
                                   __float2half_rn(a.w - __half2float(pw)));
    // bf16 split
    __nv_bfloat16 qx = __float2bfloat16(a.x), qy = __float2bfloat16(a.y);
    __nv_bfloat16 qz = __float2bfloat16(a.z), qw = __float2bfloat16(a.w);
    bh[2 * i]     = __halves2bfloat162(qx, qy);
    bh[2 * i + 1] = __halves2bfloat162(qz, qw);
    bl[2 * i]     = __halves2bfloat162(__float2bfloat16(a.x - __bfloat162float(qx)),
                                       __float2bfloat16(a.y - __bfloat162float(qy)));
    bl[2 * i + 1] = __halves2bfloat162(__float2bfloat16(a.z - __bfloat162float(qz)),
                                       __float2bfloat16(a.w - __bfloat162float(qw)));
}

// fp32 -> bf16 hi/lo split (Wf1, Wf2, f1)
__global__ void split_kernel(const float4* __restrict__ in,
                             __nv_bfloat162* __restrict__ hi,
                             __nv_bfloat162* __restrict__ lo, int n4)
{
    int i = blockIdx.x * blockDim.x + threadIdx.x;
    if (i >= n4) return;
    float4 a = in[i];
    __nv_bfloat16 hx = __float2bfloat16(a.x);
    __nv_bfloat16 hy = __float2bfloat16(a.y);
    __nv_bfloat16 hz = __float2bfloat16(a.z);
    __nv_bfloat16 hw = __float2bfloat16(a.w);
    hi[2 * i]     = __halves2bfloat162(hx, hy);
    hi[2 * i + 1] = __halves2bfloat162(hz, hw);
    lo[2 * i]     = __halves2bfloat162(__float2bfloat16(a.x - __bfloat162float(hx)),
                                       __float2bfloat16(a.y - __bfloat162float(hy)));
    lo[2 * i + 1] = __halves2bfloat162(__float2bfloat16(a.z - __bfloat162float(hz)),
                                       __float2bfloat16(a.w - __bfloat162float(hw)));
}

// fp32 -> fp16 single (weights)
__global__ void cvtH_kernel(const float4* __restrict__ in,
                            __half2* __restrict__ out, int n4)
{
    int i = blockIdx.x * blockDim.x + threadIdx.x;
    if (i >= n4) return;
    float4 a = in[i];
    out[2 * i]     = __halves2half2(__float2half_rn(a.x), __float2half_rn(a.y));
    out[2 * i + 1] = __halves2half2(__float2half_rn(a.z), __float2half_rn(a.w));
}

// ---------------------------------------------------------------------------
// fp16 2-pass batched tensor GEMM: C[z] = (Ah + Al) @ B[z]
// ---------------------------------------------------------------------------
#define BKC 32
#define A_STR 40
#define B_STR 136
#define HSLOT_A (128 * A_STR * 2)       // 10240
#define HSLOT_B (BKC * B_STR * 2)       // 8704
#define HBUF (2 * HSLOT_A + HSLOT_B)    // 29184
#define HOFF_AH(buf) ((buf) * HBUF)
#define HOFF_B(buf)  ((buf) * HBUF + 2 * HSLOT_A)
#define HGEMM_SMEM (2 * HBUF)           // 58368

struct HGemmTriple {
    const __half* B;
    float* C;
};
struct HGemmBatch {
    const __half* Ah;
    const __half* Al;
    HGemmTriple t[4];
};

__device__ __forceinline__ void hgemm_load(
    uint32_t sb, int buf,
    const __half* __restrict__ Ah, const __half* __restrict__ Al,
    const __half* __restrict__ B,
    int m0, int n0, int k0, int K, int N, int tid)
{
#pragma unroll
    for (int r = 0; r < 2; r++) {
        int i = tid + (r << 8);
        int row = i >> 2;
        int kc  = (i & 3) << 3;
        uint32_t da = sb + HOFF_AH(buf) + row * (A_STR * 2) + kc * 2;
        CP16(da,           (const void*)(Ah + (size_t)(m0 + row) * K + k0 + kc));
        CP16(da + HSLOT_A, (const void*)(Al + (size_t)(m0 + row) * K + k0 + kc));
    }
#pragma unroll
    for (int r = 0; r < 2; r++) {
        int i = tid + (r << 8);
        int krow = i >> 4;
        int nc   = (i & 15) << 3;
        uint32_t db = sb + HOFF_B(buf) + krow * (B_STR * 2) + nc * 2;
        CP16(db, (const void*)(B + (size_t)(k0 + krow) * N + n0 + nc));
    }
}

__global__ void __launch_bounds__(256, 2)
hgemm_kernel(HGemmBatch gbat, int M, int N, int K)
{
    extern __shared__ char smem[];
    const uint32_t sb = smem_u32(smem);
    const int tid  = threadIdx.x;
    const int lane = tid & 31;
    const int wid  = tid >> 5;
    const int wm0  = (wid >> 2) * 64;
    const int wn0  = (wid & 3) * 32;
    const int m0 = blockIdx.y * 128;
    const int n0 = blockIdx.x * 128;

    const __half* __restrict__ Ah = gbat.Ah;
    const __half* __restrict__ Al = gbat.Al;
    const __half* __restrict__ B  = gbat.t[blockIdx.z].B;
    float* __restrict__ C = gbat.t[blockIdx.z].C;

    float acc[4][4][4];
#pragma unroll
    for (int a = 0; a < 4; a++)
#pragma unroll
        for (int b = 0; b < 4; b++)
#pragma unroll
            for (int c = 0; c < 4; c++) acc[a][b][c] = 0.f;

    const int nch = K / BKC;
    hgemm_load(sb, 0, Ah, Al, B, m0, n0, 0, K, N, tid);
    CP_COMMIT();

    for (int ch = 0; ch < nch; ch++) {
        const int buf = ch & 1;
        if (ch + 1 < nch) {
            hgemm_load(sb, buf ^ 1, Ah, Al, B, m0, n0, (ch + 1) * BKC, K, N, tid);
            CP_COMMIT();
            CP_WAIT1();
        } else {
            CP_WAIT0();
        }
        __syncthreads();

        const uint32_t aBase = sb + HOFF_AH(buf);
        const uint32_t bBase = sb + HOFF_B(buf);

#pragma unroll
        for (int kk = 0; kk < 2; kk++) {
            const int kb = kk * 16;
            uint32_t Af[4][4], Bf[2][4];

            const int arow = wm0 + (lane & 15);
            const uint32_t kcol = (uint32_t)(kb + ((lane >> 4) << 3)) * 2;
            const int krow = kb + (lane & 15);

#pragma unroll
            for (int nb2 = 0; nb2 < 2; nb2++) {
                uint32_t nby = (uint32_t)(wn0 + nb2 * 16 + ((lane >> 4) << 3)) * 2;
                LDSM4T(Bf[nb2], bBase + (uint32_t)krow * (B_STR * 2) + nby);
            }
#pragma unroll
            for (int mb = 0; mb < 4; mb++) {
                uint32_t ad = aBase + (uint32_t)(arow + mb * 16) * (A_STR * 2) + kcol;
                LDSM4(Af[mb], ad);
            }
#pragma unroll
            for (int mb = 0; mb < 4; mb++) {
#pragma unroll
                for (int nb = 0; nb < 4; nb++) {
                    uint32_t b0 = Bf[nb >> 1][(nb & 1) << 1];
                    uint32_t b1 = Bf[nb >> 1][((nb & 1) << 1) | 1];
                    MMA_F16(acc[mb][nb], Af[mb], b0, b1);
                }
            }
#pragma unroll
            for (int mb = 0; mb < 4; mb++) {
                uint32_t ad = aBase + HSLOT_A
                            + (uint32_t)(arow + mb * 16) * (A_STR * 2) + kcol;
                LDSM4(Af[mb], ad);
            }
#pragma unroll
            for (int mb = 0; mb < 4; mb++) {
#pragma unroll
                for (int nb = 0; nb < 4; nb++) {
                    uint32_t b0 = Bf[nb >> 1][(nb & 1) << 1];
                    uint32_t b1 = Bf[nb >> 1][((nb & 1) << 1) | 1];
                    MMA_F16(acc[mb][nb], Af[mb], b0, b1);
                }
            }
        }
        __syncthreads();
    }

#pragma unroll
    for (int mb = 0; mb < 4; mb++) {
#pragma unroll
        for (int nb = 0; nb < 4; nb++) {
            int r = m0 + wm0 + mb * 16 + (lane >> 2);
            int c = n0 + wn0 + nb * 8 + ((lane & 3) << 1);
            float2 v0 = make_float2(acc[mb][nb][0], acc[mb][nb][1]);
            float2 v1 = make_float2(acc[mb][nb][2], acc[mb][nb][3]);
            *(float2*)&C[(size_t)r * N + c]       = v0;
            *(float2*)&C[(size_t)(r + 8) * N + c] = v1;
        }
    }
}

// ---------------------------------------------------------------------------
// bf16-split 3-pass tensor GEMM (gate path). GEXP=true fuses the KDA decay
// transform exp(-exp(A_log[h]) * softplus(val + dt_bias[c])) into the epilogue.
// ---------------------------------------------------------------------------
#define SA_SLOT (128 * A_STR * 2)
#define SB_SLOT (BKC * B_STR * 2)
#define ABYTES (4 * SA_SLOT)
#define OFF_A(buf, hl) ((buf) * 2 * SA_SLOT + (hl) * SA_SLOT)
#define OFF_B(buf, hl) (ABYTES + (buf) * 2 * SB_SLOT + (hl) * SB_SLOT)
#define GEMM_SMEM (ABYTES + 4 * SB_SLOT)

__device__ __forceinline__ void gemm_load_chunk(
    uint32_t sb, int buf,
    const __nv_bfloat16* __restrict__ Ah, const __nv_bfloat16* __restrict__ Al,
    const __nv_bfloat16* __restrict__ Bh, const __nv_bfloat16* __restrict__ Bl,
    int m0, int n0, int k0, int K, int N, int tid)
{
#pragma unroll
    for (int r = 0; r < 2; r++) {
        int i = tid + (r << 8);
        int row = i >> 2;
        int kc  = (i & 3) << 3;
        uint32_t da = sb + OFF_A(buf, 0) + row * (A_STR * 2) + kc * 2;
        CP16(da, (const void*)(Ah + (size_t)(m0 + row) * K + k0 + kc));
        CP16(da + SA_SLOT, (const void*)(Al + (size_t)(m0 + row) * K + k0 + kc));
    }
#pragma unroll
    for (int r = 0; r < 2; r++) {
        int i = tid + (r << 8);
        int krow = i >> 4;
        int nc   = (i & 15) << 3;
        uint32_t db = sb + OFF_B(buf, 0) + krow * (B_STR * 2) + nc * 2;
        CP16(db, (const void*)(Bh + (size_t)(k0 + krow) * N + n0 + nc));
        CP16(db + SB_SLOT, (const void*)(Bl + (size_t)(k0 + krow) * N + n0 + nc));
    }
}

template <bool GEXP>
__global__ void __launch_bounds__(256, 2)
tgemm_kernel(const __nv_bfloat16* __restrict__ Ah,
             const __nv_bfloat16* __restrict__ Al,
             const __nv_bfloat16* __restrict__ Bh,
             const __nv_bfloat16* __restrict__ Bl,
             float* __restrict__ C, int M, int N, int K,
             const float* __restrict__ A_log,
             const float* __restrict__ dt_bias)
{
    extern __shared__ char smem[];
    const uint32_t sb = smem_u32(smem);
    const int tid  = threadIdx.x;
    const int lane = tid & 31;
    const int wid  = tid >> 5;
    const int wm0  = (wid >> 2) * 64;
    const int wn0  = (wid & 3) * 32;
    const int m0 = blockIdx.y * 128;
    const int n0 = blockIdx.x * 128;

    float acc[4][4][4];
#pragma unroll
    for (int a = 0; a < 4; a++)
#pragma unroll
        for (int b = 0; b < 4; b++)
#pragma unroll
            for (int c = 0; c < 4; c++) acc[a][b][c] = 0.f;

    const int nch = K / BKC;
    gemm_load_chunk(sb, 0, Ah, Al, Bh, Bl, m0, n0, 0, K, N, tid);
    CP_COMMIT();

    for (int ch = 0; ch < nch; ch++) {
        const int buf = ch & 1;
        if (ch + 1 < nch) {
            gemm_load_chunk(sb, buf ^ 1, Ah, Al, Bh, Bl,
                            m0, n0, (ch + 1) * BKC, K, N, tid);
            CP_COMMIT();
            CP_WAIT1();
        } else {
            CP_WAIT0();
        }
        __syncthreads();

        const uint32_t aBase = sb + OFF_A(buf, 0);
        const uint32_t bBase = sb + OFF_B(buf, 0);

#pragma unroll
        for (int kk = 0; kk < 2; kk++) {
            const int kb = kk * 16;
            uint32_t Af[4][4], Bhf[2][4], Blf[2][4];
            const int arow = wm0 + (lane & 15);
            const uint32_t kcol = (uint32_t)(kb + ((lane >> 4) << 3)) * 2;
            const int krow = kb + (lane & 15);

#pragma unroll
            for (int nb2 = 0; nb2 < 2; nb2++) {
                uint32_t nby = (uint32_t)(wn0 + nb2 * 16 + ((lane >> 4) << 3)) * 2;
                uint32_t bd = bBase + (uint32_t)krow * (B_STR * 2) + nby;
                LDSM4T(Bhf[nb2], bd);
                LDSM4T(Blf[nb2], bd + SB_SLOT);
            }
#pragma unroll
            for (int mb = 0; mb < 4; mb++) {
                uint32_t ad = aBase + (uint32_t)(arow + mb * 16) * (A_STR * 2) + kcol;
                LDSM4(Af[mb], ad);
            }
#pragma unroll
            for (int mb = 0; mb < 4; mb++) {
#pragma unroll
                for (int nb = 0; nb < 4; nb++) {
                    uint32_t bh0 = Bhf[nb >> 1][(nb & 1) << 1];
                    uint32_t bh1 = Bhf[nb >> 1][((nb & 1) << 1) | 1];
                    uint32_t bl0 = Blf[nb >> 1][(nb & 1) << 1];
                    uint32_t bl1 = Blf[nb >> 1][((nb & 1) << 1) | 1];
                    MMA_BF16(acc[mb][nb], Af[mb], bh0, bh1);
                    MMA_BF16(acc[mb][nb], Af[mb], bl0, bl1);
                }
            }
#pragma unroll
            for (int mb = 0; mb < 4; mb++) {
                uint32_t ad = aBase + SA_SLOT
                            + (uint32_t)(arow + mb * 16) * (A_STR * 2) + kcol;
                LDSM4(Af[mb], ad);
            }
#pragma unroll
            for (int mb = 0; mb < 4; mb++) {
#pragma unroll
                for (int nb = 0; nb < 4; nb++) {
                    uint32_t bh0 = Bhf[nb >> 1][(nb & 1) << 1];
                    uint32_t bh1 = Bhf[nb >> 1][((nb & 1) << 1) | 1];
                    MMA_BF16(acc[mb][nb], Af[mb], bh0, bh1);
                }
            }
        }
        __syncthreads();
    }

#pragma unroll
    for (int mb = 0; mb < 4; mb++) {
#pragma unroll
        for (int nb = 0; nb < 4; nb++) {
            int r = m0 + wm0 + mb * 16 + (lane >> 2);
            int c = n0 + wn0 + nb * 8 + ((lane & 3) << 1);
            float v[4] = { acc[mb][nb][0], acc[mb][nb][1],
                           acc[mb][nb][2], acc[mb][nb][3] };
            if (GEXP) {
                float a = -expf(A_log[c >> 7]);     // c, c+1 share h (c even, 8-aligned pairs)
                float d0 = dt_bias[c], d1 = dt_bias[c + 1];
#pragma unroll
                for (int j = 0; j < 4; j++) {
                    float u = v[j] + ((j & 1) ? d1 : d0);
                    float sp = (u > 20.f) ? u : log1pf(expf(u));
                    v[j] = expf(a * sp);
                }
            }
            *(float2*)&C[(size_t)r * N + c]       = make_float2(v[0], v[1]);
            *(float2*)&C[(size_t)(r + 8) * N + c] = make_float2(v[2], v[3]);
        }
    }
}

// ---------------------------------------------------------------------------
// beta = sigmoid(x @ Wb) — coalesced rewrite.
// Block 256 = 16 k-groups x 16 heads. Wb rows are 64B; a warp covers 2
// consecutive k rows fully coalesced; x broadcast within each 16-group.
// ---------------------------------------------------------------------------
__global__ __launch_bounds__(256) void beta_kernel(
    const float* __restrict__ x, const float* __restrict__ Wb,
    float* __restrict__ beta)
{
    const int m = blockIdx.x;
    const int tid = threadIdx.x;
    const int h = tid & 15;
    const int g = tid >> 4;          // 0..15
    const float* xr = x + (size_t)m * DIM;

    float acc = 0.f;
    for (int k = g; k < DIM; k += 16)
        acc += xr[k] * Wb[k * NH + h];

    __shared__ float sh[16][17];
    sh[g][h] = acc;
    __syncthreads();
    if (tid < NH) {
        float s = 0.f;
#pragma unroll
        for (int i = 0; i < 16; i++) s += sh[i][tid];
        beta[(size_t)m * NH + tid] = 1.f / (1.f + expf(-s));
    }
}

// ---------------------------------------------------------------------------
// Causal depthwise conv (K=4) + SiLU (+ per-head L2 norm)
// ---------------------------------------------------------------------------
template <bool NORM>
__global__ __launch_bounds__(128) void conv_kernel(
    const float* __restrict__ xin, const float* __restrict__ w,
    float* __restrict__ out)
{
    const int TT = 32;
    const int t0 = blockIdx.x * TT;
    const int c0 = blockIdx.y * 128;
    const int b  = blockIdx.z;
    const int tid = threadIdx.x;
    const int c = c0 + tid;

    __shared__ float xsh[TT + 3][128];
    __shared__ float ysh[TT][128];
    __shared__ float rns[TT];

    const float* xb = xin + ((size_t)b * SEQ) * DIM + c;
#pragma unroll
    for (int r = 0; r < TT + 3; r++) {
        int t = t0 - 3 + r;
        xsh[r][tid] = (t >= 0) ? xb[(size_t)t * DIM] : 0.f;
    }
    float4 wv = *(const float4*)(w + (size_t)c * 4);
    __syncthreads();

    float yreg[TT];
#pragma unroll
    for (int tt = 0; tt < TT; tt++) {
        float y = xsh[tt][tid] * wv.x + xsh[tt + 1][tid] * wv.y
                + xsh[tt + 2][tid] * wv.z + xsh[tt + 3][tid] * wv.w;
        y = y / (1.f + expf(-y));
        yreg[tt] = y;
        if (NORM) ysh[tt][tid] = y;
    }

    if (NORM) {
        __syncthreads();
        const int wd = tid >> 5, lane = tid & 31;
        for (int tt = wd; tt < TT; tt += 4) {
            float a0 = ysh[tt][lane],      a1 = ysh[tt][lane + 32];
            float a2 = ysh[tt][lane + 64], a3 = ysh[tt][lane + 96];
            float s = a0 * a0 + a1 * a1 + a2 * a2 + a3 * a3;
#pragma unroll
            for (int off = 16; off > 0; off >>= 1)
                s += __shfl_xor_sync(0xFFFFFFFFu, s, off);
            if (lane == 0) rns[tt] = rsqrtf(s + 1e-6f);
        }
        __syncthreads();
    }

    float* ob = out + ((size_t)b * SEQ) * DIM + c;
#pragma unroll
    for (int tt = 0; tt < TT; tt++) {
        float y = yreg[tt];
        if (NORM) y *= rns[tt];
        ob[(size_t)(t0 + tt) * DIM] = y;
    }
}

// ---------------------------------------------------------------------------
// Delta-rule scan, barrier-free.
// ---------------------------------------------------------------------------
#define SCAN_LOAD(J, qb_, kb_, gb_, vt_, bt_, tt)                              \
    do {                                                                       \
        const float4* _qp = qp + (size_t)(tt) * ST4;                           \
        const float4* _kp = kp + (size_t)(tt) * ST4;                           \
        const float4* _gp = gp + (size_t)(tt) * ST4;                           \
        _Pragma("unroll")                                                      \
        for (int j = 0; j < 4; j++) {                                          \
            qb_[j] = _qp[j]; kb_[j] = _kp[j]; gb_[j] = _gp[j];                 \
        }                                                                      \
        vt_ = v[vbase + (size_t)(tt) * (NH * DV)];                             \
        bt_ = beta[bbase + (size_t)(tt) * NH];                                 \
    } while (0)

#define SCAN_STEP(qb_, kb_, gb_, vt_, bt_, tt)                                 \
    do {                                                                       \
        float kv0 = 0.f, kv1 = 0.f, kv2 = 0.f, kv3 = 0.f;                      \
        _Pragma("unroll")                                                      \
        for (int ii = 0; ii < 4; ii++) {                                       \
            float4 kk4 = kb_[ii]; float4 gg4 = gb_[ii];                        \
            S[4*ii+0] *= gg4.x; kv0 += kk4.x * S[4*ii+0];                      \
            S[4*ii+1] *= gg4.y; kv1 += kk4.y * S[4*ii+1];                      \
            S[4*ii+2] *= gg4.z; kv2 += kk4.z * S[4*ii+2];                      \
            S[4*ii+3] *= gg4.w; kv3 += kk4.w * S[4*ii+3];                      \
        }                                                                      \
        float kv = (kv0 + kv1) + (kv2 + kv3);                                  \
        kv += __shfl_xor_sync(0xFFFFFFFFu, kv, 1);                             \
        kv += __shfl_xor_sync(0xFFFFFFFFu, kv, 2);                             \
        kv += __shfl_xor_sync(0xFFFFFFFFu, kv, 4);                             \
        float upd = (vt_ - kv) * bt_;                                          \
        float ov0 = 0.f, ov1 = 0.f, ov2 = 0.f, ov3 = 0.f;                      \
        _Pragma("unroll")                                                      \
        for (int ii = 0; ii < 4; ii++) {                                       \
            float4 kk4 = kb_[ii]; float4 qq4 = qb_[ii];                        \
            S[4*ii+0] += kk4.x * upd; ov0 += qq4.x * S[4*ii+0];                \
            S[4*ii+1] += kk4.y * upd; ov1 += qq4.y * S[4*ii+1];                \
            S[4*ii+2] += kk4.z * upd; ov2 += qq4.z * S[4*ii+2];                \
            S[4*ii+3] += kk4.w * upd; ov3 += qq4.w * S[4*ii+3];                \
        }                                                                      \
        float ov = (ov0 + ov1) + (ov2 + ov3);                                  \
        ov += __shfl_xor_sync(0xFFFFFFFFu, ov, 1);                             \
        ov += __shfl_xor_sync(0xFFFFFFFFu, ov, 2);                             \
        ov += __shfl_xor_sync(0xFFFFFFFFu, ov, 4);                             \
        if (s == 0) o[vbase + (size_t)(tt) * (NH * DV)] = ov * scale;          \
    } while (0)

__global__ __launch_bounds__(256) void scan_kernel(
    const float* __restrict__ q, const float* __restrict__ k,
    const float* __restrict__ v, const float* __restrict__ ge,
    const float* __restrict__ beta, float* __restrict__ o)
{
    const int bh = blockIdx.x >> 2;
    const int cg = blockIdx.x & 3;
    const int b  = bh / NH, h = bh % NH;
    const int tid = threadIdx.x;
    const int s   = tid & 7;
    const int col = cg * 32 + (tid >> 3);

    const float scale = 0.08838834764831845f;
    const size_t kbase = ((size_t)(b * SEQ) * NH + h) * (size_t)DK + s * 16;
    const size_t vbase = ((size_t)(b * SEQ) * NH + h) * (size_t)DV + col;
    const size_t bbase = (size_t)(b * SEQ) * NH + h;
    const int ST4 = (NH * DK) / 4;

    const float4* qp = (const float4*)(q + kbase);
    const float4* kp = (const float4*)(k + kbase);
    const float4* gp = (const float4*)(ge + kbase);

    float S[16];
#pragma unroll
    for (int i = 0; i < 16; i++) S[i] = 0.f;

    float4 q0[4], k0[4], g0[4], q1[4], k1[4], g1[4];
    float vt0, bt0, vt1, bt1;

    SCAN_LOAD(0, q0, k0, g0, vt0, bt0, 0);

    for (int t = 0; t < SEQ; t += 2) {
        SCAN_LOAD(1, q1, k1, g1, vt1, bt1, t + 1);
        SCAN_STEP(q0, k0, g0, vt0, bt0, t);
        if (t + 2 < SEQ)
            SCAN_LOAD(0, q0, k0, g0, vt0, bt0, t + 2);
        SCAN_STEP(q1, k1, g1, vt1, bt1, t + 1);
    }
}

// ---------------------------------------------------------------------------
// Epilogue: gated RMSNorm, fused with fp16 hi/lo split of the result
// ---------------------------------------------------------------------------
__global__ __launch_bounds__(128) void epilogue_kernel(
    const float* __restrict__ o, const float* __restrict__ gate,
    const float* __restrict__ bg, const float* __restrict__ onw,
    __half* __restrict__ oh, __half* __restrict__ ol)
{
    const int m = blockIdx.x;
    const int h = blockIdx.y;
    const int tid = threadIdx.x;
    size_t idx = ((size_t)m * NH + h) * (size_t)DV + tid;

    float ov = o[idx];
    float s = ov * ov;
#pragma unroll
    for (int off = 16; off > 0; off >>= 1)
        s += __shfl_xor_sync(0xFFFFFFFFu, s, off);

    __shared__ float ws[4];
    const int wd = tid >> 5, lane = tid & 31;
    if (lane == 0) ws[wd] = s;
    __syncthreads();
    float tot = ws[0] + ws[1] + ws[2] + ws[3];

    float r = rsqrtf(tot * (1.f / 128.f) + 1e-5f);
    float gv = gate[idx] + bg[h * DV + tid];
    float sig = 1.f / (1.f + expf(-gv));
    float f = ov * r * onw[tid] * (gv * sig);

    __half fh = __float2half_rn(f);
    oh[idx] = fh;
    ol[idx] = __float2half_rn(f - __half2float(fh));
}

// ---------------------------------------------------------------------------
// kernel_launch
// NOTE: launch order deliberate — ncu (-s 5 -c 1) captures launch index 5,
// arranged to be the batched QKVG hgemm.
// ---------------------------------------------------------------------------
static inline void do_split(const float* src, __nv_bfloat16* hi,
                            __nv_bfloat16* lo, int n)
{
    int n4 = n >> 2;
    split_kernel<<<(n4 + 255) / 256, 256>>>(
        (const float4*)src, (__nv_bfloat162*)hi, (__nv_bfloat162*)lo, n4);
}

static inline void do_cvtH(const float* src, __half* dst, int n)
{
    int n4 = n >> 2;
    cvtH_kernel<<<(n4 + 255) / 256, 256>>>(
        (const float4*)src, (__half2*)dst, n4);
}

extern "C" void kernel_launch(void* const* d_in, const int* in_sizes, int n_in,
                              void* d_out, int out_size)
{
    const float* x       = (const float*)d_in[0];
    const float* Wq      = (const float*)d_in[1];
    const float* Wk      = (const float*)d_in[2];
    const float* Wv      = (const float*)d_in[3];
    const float* conv_q  = (const float*)d_in[4];
    const float* conv_k  = (const float*)d_in[5];
    const float* conv_v  = (const float*)d_in[6];
    const float* Wf1     = (const float*)d_in[7];
    const float* Wf2     = (const float*)d_in[8];
    const float* Wb      = (const float*)d_in[9];
    const float* A_log   = (const float*)d_in[10];
    const float* dt_bias = (const float*)d_in[11];
    const float* Wg      = (const float*)d_in[12];
    const float* bg      = (const float*)d_in[13];
    const float* o_norm_w= (const float*)d_in[14];
    const float* Wo      = (const float*)d_in[15];
    float* out = (float*)d_out;

    cudaFuncSetAttribute(tgemm_kernel<false>,
                         cudaFuncAttributeMaxDynamicSharedMemorySize, GEMM_SMEM);
    cudaFuncSetAttribute(tgemm_kernel<true>,
                         cudaFuncAttributeMaxDynamicSharedMemorySize, GEMM_SMEM);
    cudaFuncSetAttribute(hgemm_kernel,
                         cudaFuncAttributeMaxDynamicSharedMemorySize, HGEMM_SMEM);

    float *qpre, *kpre, *vpre, *qb, *kb, *vb, *gateb, *gb, *ob, *f1b, *betab;
    cudaGetSymbolAddress((void**)&qpre,  g_qpre);
    cudaGetSymbolAddress((void**)&kpre,  g_kpre);
    cudaGetSymbolAddress((void**)&vpre,  g_vpre);
    cudaGetSymbolAddress((void**)&qb,    g_q);
    cudaGetSymbolAddress((void**)&kb,    g_k);
    cudaGetSymbolAddress((void**)&vb,    g_v);
    cudaGetSymbolAddress((void**)&gateb, g_gate);
    cudaGetSymbolAddress((void**)&gb,    g_g);
    cudaGetSymbolAddress((void**)&ob,    g_o);
    cudaGetSymbolAddress((void**)&f1b,   g_f1);
    cudaGetSymbolAddress((void**)&betab, g_beta);

    __nv_bfloat16 *xbh, *xbl, *wf1h, *wf1l, *wf2h, *wf2l, *f1h, *f1l;
    cudaGetSymbolAddress((void**)&xbh,  g_xbh);  cudaGetSymbolAddress((void**)&xbl,  g_xbl);
    cudaGetSymbolAddress((void**)&wf1h, g_wf1h); cudaGetSymbolAddress((void**)&wf1l, g_wf1l);
    cudaGetSymbolAddress((void**)&wf2h, g_wf2h); cudaGetSymbolAddress((void**)&wf2l, g_wf2l);
    cudaGetSymbolAddress((void**)&f1h,  g_f1h);  cudaGetSymbolAddress((void**)&f1l,  g_f1l);

    __half *xhh, *xhl, *ohh, *ohl, *hwq, *hwk, *hwv, *hwg, *hwo;
    cudaGetSymbolAddress((void**)&xhh, g_xhh); cudaGetSymbolAddress((void**)&xhl, g_xhl);
    cudaGetSymbolAddress((void**)&ohh, g_ohh); cudaGetSymbolAddress((void**)&ohl, g_ohl);
    cudaGetSymbolAddress((void**)&hwq, g_hwq); cudaGetSymbolAddress((void**)&hwk, g_hwk);
    cudaGetSymbolAddress((void**)&hwv, g_hwv); cudaGetSymbolAddress((void**)&hwg, g_hwg);
    cudaGetSymbolAddress((void**)&hwo, g_hwo);

    // launch 0: fused x split (fp16 hi/lo + bf16 hi/lo, one read pass)
    splitHB_kernel<<<(NELEM / 4 + 255) / 256, 256>>>(
        (const float4*)x, (__half2*)xhh, (__half2*)xhl,
        (__nv_bfloat162*)xbh, (__nv_bfloat162*)xbl, NELEM / 4);

    // launches 1-4: weight conversions feeding the QKVG GEMM
    do_cvtH(Wq, hwq, WSZ);
    do_cvtH(Wk, hwk, WSZ);
    do_cvtH(Wv, hwv, WSZ);
    do_cvtH(Wg, hwg, WSZ);

    // launch 5: batched QKVG projection  <-- ncu-captured launch
    {
        HGemmBatch gbat;
        gbat.Ah = xhh; gbat.Al = xhl;
        gbat.t[0] = { hwq, qpre };
        gbat.t[1] = { hwk, kpre };
        gbat.t[2] = { hwv, vpre };
        gbat.t[3] = { hwg, gateb };
        dim3 g(DIM / 128, MTOT / 128, 4);
        hgemm_kernel<<<g, 256, HGEMM_SMEM>>>(gbat, MTOT, DIM, DIM);
    }

    do_cvtH(Wo, hwo, WSZ);

    // gate path (bf16 3-pass, precision-critical); gexp fused into f2 epilogue
    do_split(Wf1, wf1h, wf1l, DIM * DV);
    do_split(Wf2, wf2h, wf2l, DV * DIM);
    {
        dim3 g(DV / 128, MTOT / 128, 1);
        tgemm_kernel<false><<<g, 256, GEMM_SMEM>>>(
            xbh, xbl, wf1h, wf1l, f1b, MTOT, DV, DIM, nullptr, nullptr);
    }
    do_split(f1b, f1h, f1l, MTOT * DV);
    {
        dim3 g(DIM / 128, MTOT / 128, 1);
        tgemm_kernel<true><<<g, 256, GEMM_SMEM>>>(
            f1h, f1l, wf2h, wf2l, gb, MTOT, DIM, DV, A_log, dt_bias);
    }

    beta_kernel<<<MTOT, 256>>>(x, Wb, betab);

    // conv + silu (+ l2norm for q,k)
    dim3 gConv(SEQ / 32, DIM / 128, BATCH);
    conv_kernel<true ><<<gConv, 128>>>(qpre, conv_q, qb);
    conv_kernel<true ><<<gConv, 128>>>(kpre, conv_k, kb);
    conv_kernel<false><<<gConv, 128>>>(vpre, conv_v, vb);

    // delta-rule scan (gb already holds gexp via fused epilogue)
    scan_kernel<<<BATCH * NH * 4, 256>>>(qb, kb, vb, gb, betab, ob);

    // gated RMSNorm epilogue fused with fp16 hi/lo split
    dim3 gEpi(MTOT, NH);
    epilogue_kernel<<<gEpi, 128>>>(ob, gateb, bg, o_norm_w, ohh, ohl);

    // output projection (fp16 2-pass)
    {
        HGemmBatch gbat;
        gbat.Ah = ohh; gbat.Al = ohl;
        gbat.t[0] = { hwo, out };
        gbat.t[1] = gbat.t[0]; gbat.t[2] = gbat.t[0]; gbat.t[3] = gbat.t[0];
        dim3 g(DIM / 128, MTOT / 128, 1);
        hgemm_kernel<<<g, 256, HGEMM_SMEM>>>(gbat, MTOT, DIM, DIM);
    }
}